// round 8
// baseline (speedup 1.0000x reference)
#include <cuda_runtime.h>
#include <math.h>

#define NB 32
#define NH 32
#define DMODEL 4096
#define DKH 128
#define SINKC 4
#define WINDOWC 1020
#define MAXC (SINKC + WINDOWC)   /* 1024 */

// Scratch (device globals: no allocation allowed)
__device__ float g_proj[3 * NB * DMODEL];   // Q, K, V projections [3][B][DM]
__device__ float g_attn[NB * DMODEL];       // attention output pre-W_O
__device__ float g_cos[MAXC * 64];
__device__ float g_sin[MAXC * 64];

// ---------------------------------------------------------------------------
// RoPE tables: cos/sin(pos * theta_j), theta_j = 10000^(-j/64), fp32 like ref
// ---------------------------------------------------------------------------
__global__ void rope_table_kernel() {
    int i = blockIdx.x * blockDim.x + threadIdx.x;   // 0 .. MAXC*64-1
    int pos = i >> 6;
    int j = i & 63;
    float theta = powf(10000.0f, -(float)j / 64.0f);
    float ang = (float)pos * theta;
    float s, c;
    sincosf(ang, &s, &c);
    g_cos[i] = c;
    g_sin[i] = s;
}

// ---------------------------------------------------------------------------
// Batched GEMV core: out[b][n] = sum_k x[b][k] * W[n][k]   (b = lane, B == 32)
// W rows broadcast-loaded once per warp (streams at DRAM rate), x chunk staged
// in smem (row stride 260 floats -> conflict-light LDS.128). Each warp owns 2
// output rows; block = 8 warps = 16 rows; grid = 256 blocks covers 4096 rows.
// ---------------------------------------------------------------------------
__device__ __forceinline__ void gemv32_body(const float* __restrict__ x,
                                            const float* __restrict__ W,
                                            float* __restrict__ out) {
    __shared__ float xs[32 * 260];
    int warp = threadIdx.x >> 5;
    int lane = threadIdx.x & 31;
    int n0 = blockIdx.x * 16 + warp * 2;

    const float4* w0p = (const float4*)(W + (size_t)n0 * DMODEL);
    const float4* w1p = (const float4*)(W + (size_t)(n0 + 1) * DMODEL);
    float4 a0 = make_float4(0.f, 0.f, 0.f, 0.f);
    float4 a1 = make_float4(0.f, 0.f, 0.f, 0.f);

    for (int kc = 0; kc < DMODEL; kc += 256) {
        __syncthreads();
        #pragma unroll
        for (int i = 0; i < 8; i++) {
            int f = (i * 256 + threadIdx.x) * 4;     // float index 0..8188
            int bb = f >> 8;
            int kk = f & 255;
            *(float4*)(xs + bb * 260 + kk) =
                *(const float4*)(x + (size_t)bb * DMODEL + kc + kk);
        }
        __syncthreads();

        const float4* xr  = (const float4*)(xs + lane * 260);
        const float4* w0c = w0p + (kc >> 2);
        const float4* w1c = w1p + (kc >> 2);
        #pragma unroll 4
        for (int kk = 0; kk < 64; kk++) {
            float4 w0 = w0c[kk];
            float4 w1 = w1c[kk];
            float4 xv = xr[kk];
            a0.x += w0.x * xv.x; a0.y += w0.y * xv.y;
            a0.z += w0.z * xv.z; a0.w += w0.w * xv.w;
            a1.x += w1.x * xv.x; a1.y += w1.y * xv.y;
            a1.z += w1.z * xv.z; a1.w += w1.w * xv.w;
        }
    }
    out[(size_t)lane * DMODEL + n0]     = (a0.x + a0.y) + (a0.z + a0.w);
    out[(size_t)lane * DMODEL + n0 + 1] = (a1.x + a1.y) + (a1.z + a1.w);
}

// QKV projections: slot 0/1/2 selects destination inside g_proj.
__global__ void gemv_proj_kernel(const float* __restrict__ x,
                                 const float* __restrict__ W, int slot) {
    gemv32_body(x, W, g_proj + (size_t)slot * NB * DMODEL);
}

// Output projection: reads g_attn, writes harness d_out.
__global__ void gemv_out_kernel(const float* __restrict__ W,
                                float* __restrict__ out) {
    gemv32_body(g_attn, W, out);
}

// ---------------------------------------------------------------------------
// Attention: one block per (b,h). Warp-per-position, float4 lanes over DK.
// Caches are NOT mutated: active pos p maps to cache row c(p); the last
// active position (p = L-1) reads the freshly projected K_new / V_new.
// RoPE flip pair (d, d^64) resolved via shfl_xor(16).
// ---------------------------------------------------------------------------
__global__ void attn_kernel(const float* __restrict__ kcache,
                            const float* __restrict__ vcache,
                            const int* __restrict__ seqp) {
    __shared__ float q_rot[DKH];
    __shared__ float scores[MAXC];
    __shared__ float outp[8][DKH];
    __shared__ float red[8];

    int bh = blockIdx.x;
    int b = bh >> 5;
    int h = bh & 31;
    int tid = threadIdx.x, warp = tid >> 5, lane = tid & 31;

    int seq = *seqp;
    int L, ins, part2;
    bool full;
    if (seq < MAXC) { L = seq + 1; ins = seq; part2 = 0; full = false; }
    else { L = MAXC; ins = SINKC + (seq - SINKC) % WINDOWC; part2 = MAXC - (ins + 1); full = true; }

    const float* qsrc = g_proj + ((size_t)b * DMODEL + h * DKH);
    if (tid < DKH) {
        float qv = qsrc[tid];
        float pn = qsrc[tid ^ 64];
        int j = tid & 63;
        float c = g_cos[(L - 1) * 64 + j];
        float s = g_sin[(L - 1) * 64 + j];
        float flip = (tid < 64) ? -pn : pn;
        q_rot[tid] = qv * c + flip * s;
    }
    __syncthreads();

    float4 qf = *(const float4*)(q_rot + lane * 4);
    const float4* kbase = (const float4*)(kcache + (size_t)bh * MAXC * DKH);
    const float4* vbase = (const float4*)(vcache + (size_t)bh * MAXC * DKH);
    const float4* knew  = (const float4*)(g_proj + (size_t)NB * DMODEL + (size_t)b * DMODEL + h * DKH);
    const float4* vnew  = (const float4*)(g_proj + 2 * (size_t)NB * DMODEL + (size_t)b * DMODEL + h * DKH);
    int j4 = (lane & 15) << 2;
    float sgn = (lane < 16) ? -1.0f : 1.0f;

    // ---- pass 1: scores = (R_{L-1} q) . (R_p k) / sqrt(DK) ----
    for (int p = warp; p < L; p += 8) {
        int c = p;
        if (full && p >= SINKC)
            c = (p < SINKC + part2) ? (ins + 1 + (p - SINKC))
                                    : (SINKC + (p - SINKC - part2));
        const float4* krow = (p == L - 1) ? knew : (kbase + (size_t)c * (DKH / 4));
        float4 kv = krow[lane];
        float4 cs = *(const float4*)(g_cos + p * 64 + j4);
        float4 sn = *(const float4*)(g_sin + p * 64 + j4);
        float4 pv;
        pv.x = __shfl_xor_sync(0xffffffffu, kv.x, 16);
        pv.y = __shfl_xor_sync(0xffffffffu, kv.y, 16);
        pv.z = __shfl_xor_sync(0xffffffffu, kv.z, 16);
        pv.w = __shfl_xor_sync(0xffffffffu, kv.w, 16);
        float rx = kv.x * cs.x + sgn * pv.x * sn.x;
        float ry = kv.y * cs.y + sgn * pv.y * sn.y;
        float rz = kv.z * cs.z + sgn * pv.z * sn.z;
        float rw = kv.w * cs.w + sgn * pv.w * sn.w;
        float d = rx * qf.x + ry * qf.y + rz * qf.z + rw * qf.w;
        #pragma unroll
        for (int o = 16; o > 0; o >>= 1) d += __shfl_xor_sync(0xffffffffu, d, o);
        if (lane == 0) scores[p] = d * 0.08838834764831845f;   // 1/sqrt(128)
    }
    __syncthreads();

    // ---- softmax ----
    float m = -1e30f;
    for (int p = tid; p < L; p += 256) m = fmaxf(m, scores[p]);
    #pragma unroll
    for (int o = 16; o > 0; o >>= 1) m = fmaxf(m, __shfl_xor_sync(0xffffffffu, m, o));
    if (lane == 0) red[warp] = m;
    __syncthreads();
    m = red[0];
    #pragma unroll
    for (int w = 1; w < 8; w++) m = fmaxf(m, red[w]);

    float lsum = 0.0f;
    for (int p = tid; p < L; p += 256) {
        float e = __expf(scores[p] - m);
        scores[p] = e;
        lsum += e;
    }
    #pragma unroll
    for (int o = 16; o > 0; o >>= 1) lsum += __shfl_xor_sync(0xffffffffu, lsum, o);
    __syncthreads();                 // all reads of red (max) done; scores updated
    if (lane == 0) red[warp] = lsum;
    __syncthreads();
    float S = 0.0f;
    #pragma unroll
    for (int w = 0; w < 8; w++) S += red[w];
    float inv = 1.0f / S;

    // ---- pass 2: out = attn @ V ----
    float4 acc = make_float4(0.f, 0.f, 0.f, 0.f);
    for (int p = warp; p < L; p += 8) {
        int c = p;
        if (full && p >= SINKC)
            c = (p < SINKC + part2) ? (ins + 1 + (p - SINKC))
                                    : (SINKC + (p - SINKC - part2));
        const float4* vrow = (p == L - 1) ? vnew : (vbase + (size_t)c * (DKH / 4));
        float w8 = scores[p];
        float4 vv = vrow[lane];
        acc.x += w8 * vv.x; acc.y += w8 * vv.y;
        acc.z += w8 * vv.z; acc.w += w8 * vv.w;
    }
    *(float4*)(&outp[warp][lane * 4]) = acc;
    __syncthreads();
    if (tid < DKH) {
        float s = 0.0f;
        #pragma unroll
        for (int w = 0; w < 8; w++) s += outp[w][tid];
        g_attn[(size_t)b * DMODEL + h * DKH + tid] = s * inv;
    }
}

// ---------------------------------------------------------------------------
extern "C" void kernel_launch(void* const* d_in, const int* in_sizes, int n_in,
                              void* d_out, int out_size) {
    const float* x  = (const float*)d_in[0];
    const float* kc = (const float*)d_in[1];
    const float* vc = (const float*)d_in[2];
    const float* Wq = (const float*)d_in[3];
    const float* Wk = (const float*)d_in[4];
    const float* Wv = (const float*)d_in[5];
    const float* Wo = (const float*)d_in[6];
    const int* seqp = (const int*)d_in[7];
    float* out = (float*)d_out;

    rope_table_kernel<<<64, 1024>>>();
    gemv_proj_kernel<<<256, 256>>>(x, Wq, 0);
    gemv_proj_kernel<<<256, 256>>>(x, Wk, 1);
    gemv_proj_kernel<<<256, 256>>>(x, Wv, 2);
    attn_kernel<<<NB * NH, 256>>>(kc, vc, seqp);
    gemv_out_kernel<<<256, 256>>>(Wo, out);
}

// round 9
// speedup vs baseline: 2.0926x; 2.0926x over previous
#include <cuda_runtime.h>
#include <math.h>

#define NB 32
#define NH 32
#define DMODEL 4096
#define DKH 128
#define SINKC 4
#define WINDOWC 1020
#define MAXC (SINKC + WINDOWC)   /* 1024 */
#define KSPLIT 16
#define KCHUNK (DMODEL / KSPLIT) /* 256 */

// Scratch (device globals: no allocation allowed)
__device__ float  g_proj[3 * NB * DMODEL];          // Q, K, V projections
__device__ float  g_attn[NB * DMODEL];              // attention output pre-W_O
__device__ float  g_cos[MAXC * 64];
__device__ float  g_sin[MAXC * 64];
__device__ float2 g_xs[NB * DMODEL];                // split activations (hi,lo)
__device__ float  g_part[3 * KSPLIT * NB * DMODEL]; // GEMM K-split partials (25 MB)

// ---------------------------------------------------------------------------
__device__ __forceinline__ unsigned tf32_rna(float x) {
    unsigned r;
    asm("cvt.rna.tf32.f32 %0, %1;" : "=r"(r) : "f"(x));
    return r;
}

__device__ __forceinline__ void mma_tf32(float& d0, float& d1, float& d2, float& d3,
                                         unsigned a0, unsigned a1, unsigned a2, unsigned a3,
                                         unsigned b0, unsigned b1) {
    asm("mma.sync.aligned.m16n8k8.row.col.f32.tf32.tf32.f32 "
        "{%0,%1,%2,%3}, {%4,%5,%6,%7}, {%8,%9}, {%0,%1,%2,%3};"
        : "+f"(d0), "+f"(d1), "+f"(d2), "+f"(d3)
        : "r"(a0), "r"(a1), "r"(a2), "r"(a3), "r"(b0), "r"(b1));
}

// ---------------------------------------------------------------------------
// RoPE tables: cos/sin(pos * theta_j), theta_j = 10000^(-j/64), fp32 like ref
// ---------------------------------------------------------------------------
__global__ void rope_table_kernel() {
    int i = blockIdx.x * blockDim.x + threadIdx.x;   // 0 .. MAXC*64-1
    int pos = i >> 6;
    int j = i & 63;
    float theta = powf(10000.0f, -(float)j / 64.0f);
    float ang = (float)pos * theta;
    float s, c;
    sincosf(ang, &s, &c);
    g_cos[i] = c;
    g_sin[i] = s;
}

// ---------------------------------------------------------------------------
// Split activations into (hi, lo) tf32 pair for 3xTF32. xin == nullptr -> g_attn.
// ---------------------------------------------------------------------------
__global__ void split_kernel(const float* __restrict__ xin) {
    const float* src = xin ? xin : g_attn;
    int i = blockIdx.x * blockDim.x + threadIdx.x;   // 0 .. NB*DMODEL-1
    float v = src[i];
    unsigned hb = tf32_rna(v);
    float hf = __uint_as_float(hb);
    unsigned lb = tf32_rna(v - hf);
    g_xs[i] = make_float2(hf, __uint_as_float(lb));
}

// ---------------------------------------------------------------------------
// tf32 MMA GEMM: part[slot][ks][b][n] = sum_{k in chunk} X[b][k] * W[n][k]
// A operand = W tile (m16 = 16 output features, k8), split hi/lo on the fly.
// B operand = X (k8 x n8, n = batch), pre-split in g_xs.
// 3xTF32: D += Ah*Bh + Ah*Bl + Al*Bh  (fp32-class accuracy).
// grid = (32 m-blocks, KSPLIT, nslots); block = 256 (8 warps, warp owns m16).
// ---------------------------------------------------------------------------
__global__ void mma_gemm_kernel(const float* __restrict__ Wa,
                                const float* __restrict__ Wb,
                                const float* __restrict__ Wc) {
    int slot = blockIdx.z;
    const float* W = (slot == 0) ? Wa : (slot == 1) ? Wb : Wc;
    int warp = threadIdx.x >> 5;
    int lane = threadIdx.x & 31;
    int r = lane >> 2;          // groupID
    int c = lane & 3;           // threadID_in_group
    int n0 = (blockIdx.x * 8 + warp) * 16;
    int kb = blockIdx.y * KCHUNK;

    const float* w0p = W + (size_t)(n0 + r) * DMODEL;
    const float* w1p = W + (size_t)(n0 + r + 8) * DMODEL;

    float d[4][4];
    #pragma unroll
    for (int t = 0; t < 4; t++)
        d[t][0] = d[t][1] = d[t][2] = d[t][3] = 0.0f;

    #pragma unroll 2
    for (int k0 = kb; k0 < kb + KCHUNK; k0 += 8) {
        // A fragments from W (m16n8k8 tf32 row-major layout)
        float wa0 = w0p[k0 + c];
        float wa1 = w1p[k0 + c];
        float wa2 = w0p[k0 + c + 4];
        float wa3 = w1p[k0 + c + 4];
        unsigned ah0 = tf32_rna(wa0), ah1 = tf32_rna(wa1);
        unsigned ah2 = tf32_rna(wa2), ah3 = tf32_rna(wa3);
        unsigned al0 = tf32_rna(wa0 - __uint_as_float(ah0));
        unsigned al1 = tf32_rna(wa1 - __uint_as_float(ah1));
        unsigned al2 = tf32_rna(wa2 - __uint_as_float(ah2));
        unsigned al3 = tf32_rna(wa3 - __uint_as_float(ah3));

        #pragma unroll
        for (int t = 0; t < 4; t++) {
            // B fragments: b0 -> (k = c, batch = t*8 + r), b1 -> (k = c+4, same batch)
            float2 xb0 = g_xs[(size_t)(t * 8 + r) * DMODEL + k0 + c];
            float2 xb1 = g_xs[(size_t)(t * 8 + r) * DMODEL + k0 + c + 4];
            unsigned bh0 = __float_as_uint(xb0.x), bh1 = __float_as_uint(xb1.x);
            unsigned bl0 = __float_as_uint(xb0.y), bl1 = __float_as_uint(xb1.y);
            mma_tf32(d[t][0], d[t][1], d[t][2], d[t][3], ah0, ah1, ah2, ah3, bl0, bl1); // hi*lo
            mma_tf32(d[t][0], d[t][1], d[t][2], d[t][3], al0, al1, al2, al3, bh0, bh1); // lo*hi
            mma_tf32(d[t][0], d[t][1], d[t][2], d[t][3], ah0, ah1, ah2, ah3, bh0, bh1); // hi*hi
        }
    }

    // Store: c-fragment (m16n8): d0 -> (row n0+r, batch bt+2c); d1 -> batch+1;
    //        d2/d3 -> row n0+r+8.
    float* pp = g_part + (size_t)(slot * KSPLIT + blockIdx.y) * NB * DMODEL;
    #pragma unroll
    for (int t = 0; t < 4; t++) {
        int bt = t * 8;
        pp[(size_t)(bt + 2 * c)     * DMODEL + n0 + r]     = d[t][0];
        pp[(size_t)(bt + 2 * c + 1) * DMODEL + n0 + r]     = d[t][1];
        pp[(size_t)(bt + 2 * c)     * DMODEL + n0 + r + 8] = d[t][2];
        pp[(size_t)(bt + 2 * c + 1) * DMODEL + n0 + r + 8] = d[t][3];
    }
}

// ---------------------------------------------------------------------------
// Reduce KSPLIT partials. dst == nullptr -> g_proj. Layout [slot][b][n].
// ---------------------------------------------------------------------------
__global__ void reduce_kernel(float* __restrict__ dstp, int nslots) {
    float* dst = dstp ? dstp : g_proj;
    int i = blockIdx.x * blockDim.x + threadIdx.x;   // over nslots*NB*DMODEL/4
    int per_slot = NB * (DMODEL / 4);
    if (i >= nslots * per_slot) return;
    int slot = i / per_slot;
    int rem = i - slot * per_slot;
    const float4* src = (const float4*)g_part + (size_t)slot * KSPLIT * per_slot + rem;
    float4 s = make_float4(0.f, 0.f, 0.f, 0.f);
    #pragma unroll
    for (int k = 0; k < KSPLIT; k++) {
        float4 v = src[(size_t)k * per_slot];
        s.x += v.x; s.y += v.y; s.z += v.z; s.w += v.w;
    }
    ((float4*)dst)[i] = s;
}

// ---------------------------------------------------------------------------
// Attention: one block per (b,h). Warp-per-position, float4 lanes over DK.
// Caches are NOT mutated: active pos p maps to cache row c(p); the last
// active position (p = L-1) reads the freshly projected K_new / V_new.
// RoPE flip pair (d, d^64) resolved via shfl_xor(16).
// ---------------------------------------------------------------------------
__global__ void attn_kernel(const float* __restrict__ kcache,
                            const float* __restrict__ vcache,
                            const int* __restrict__ seqp) {
    __shared__ float q_rot[DKH];
    __shared__ float scores[MAXC];
    __shared__ float outp[8][DKH];
    __shared__ float red[8];

    int bh = blockIdx.x;
    int b = bh >> 5;
    int h = bh & 31;
    int tid = threadIdx.x, warp = tid >> 5, lane = tid & 31;

    int seq = *seqp;
    int L, ins, part2;
    bool full;
    if (seq < MAXC) { L = seq + 1; ins = seq; part2 = 0; full = false; }
    else { L = MAXC; ins = SINKC + (seq - SINKC) % WINDOWC; part2 = MAXC - (ins + 1); full = true; }

    const float* qsrc = g_proj + ((size_t)b * DMODEL + h * DKH);
    if (tid < DKH) {
        float qv = qsrc[tid];
        float pn = qsrc[tid ^ 64];
        int j = tid & 63;
        float c = g_cos[(L - 1) * 64 + j];
        float s = g_sin[(L - 1) * 64 + j];
        float flip = (tid < 64) ? -pn : pn;
        q_rot[tid] = qv * c + flip * s;
    }
    __syncthreads();

    float4 qf = *(const float4*)(q_rot + lane * 4);
    const float4* kbase = (const float4*)(kcache + (size_t)bh * MAXC * DKH);
    const float4* vbase = (const float4*)(vcache + (size_t)bh * MAXC * DKH);
    const float4* knew  = (const float4*)(g_proj + (size_t)NB * DMODEL + (size_t)b * DMODEL + h * DKH);
    const float4* vnew  = (const float4*)(g_proj + 2 * (size_t)NB * DMODEL + (size_t)b * DMODEL + h * DKH);
    int j4 = (lane & 15) << 2;
    float sgn = (lane < 16) ? -1.0f : 1.0f;

    // ---- pass 1: scores = (R_{L-1} q) . (R_p k) / sqrt(DK) ----
    for (int p = warp; p < L; p += 8) {
        int c = p;
        if (full && p >= SINKC)
            c = (p < SINKC + part2) ? (ins + 1 + (p - SINKC))
                                    : (SINKC + (p - SINKC - part2));
        const float4* krow = (p == L - 1) ? knew : (kbase + (size_t)c * (DKH / 4));
        float4 kv = krow[lane];
        float4 cs = *(const float4*)(g_cos + p * 64 + j4);
        float4 sn = *(const float4*)(g_sin + p * 64 + j4);
        float4 pv;
        pv.x = __shfl_xor_sync(0xffffffffu, kv.x, 16);
        pv.y = __shfl_xor_sync(0xffffffffu, kv.y, 16);
        pv.z = __shfl_xor_sync(0xffffffffu, kv.z, 16);
        pv.w = __shfl_xor_sync(0xffffffffu, kv.w, 16);
        float rx = kv.x * cs.x + sgn * pv.x * sn.x;
        float ry = kv.y * cs.y + sgn * pv.y * sn.y;
        float rz = kv.z * cs.z + sgn * pv.z * sn.z;
        float rw = kv.w * cs.w + sgn * pv.w * sn.w;
        float d = rx * qf.x + ry * qf.y + rz * qf.z + rw * qf.w;
        #pragma unroll
        for (int o = 16; o > 0; o >>= 1) d += __shfl_xor_sync(0xffffffffu, d, o);
        if (lane == 0) scores[p] = d * 0.08838834764831845f;   // 1/sqrt(128)
    }
    __syncthreads();

    // ---- softmax ----
    float m = -1e30f;
    for (int p = tid; p < L; p += 256) m = fmaxf(m, scores[p]);
    #pragma unroll
    for (int o = 16; o > 0; o >>= 1) m = fmaxf(m, __shfl_xor_sync(0xffffffffu, m, o));
    if (lane == 0) red[warp] = m;
    __syncthreads();
    m = red[0];
    #pragma unroll
    for (int w = 1; w < 8; w++) m = fmaxf(m, red[w]);

    float lsum = 0.0f;
    for (int p = tid; p < L; p += 256) {
        float e = __expf(scores[p] - m);
        scores[p] = e;
        lsum += e;
    }
    #pragma unroll
    for (int o = 16; o > 0; o >>= 1) lsum += __shfl_xor_sync(0xffffffffu, lsum, o);
    __syncthreads();                 // all reads of red (max) done; scores updated
    if (lane == 0) red[warp] = lsum;
    __syncthreads();
    float S = 0.0f;
    #pragma unroll
    for (int w = 0; w < 8; w++) S += red[w];
    float inv = 1.0f / S;

    // ---- pass 2: out = attn @ V ----
    float4 acc = make_float4(0.f, 0.f, 0.f, 0.f);
    for (int p = warp; p < L; p += 8) {
        int c = p;
        if (full && p >= SINKC)
            c = (p < SINKC + part2) ? (ins + 1 + (p - SINKC))
                                    : (SINKC + (p - SINKC - part2));
        const float4* vrow = (p == L - 1) ? vnew : (vbase + (size_t)c * (DKH / 4));
        float w8 = scores[p];
        float4 vv = vrow[lane];
        acc.x += w8 * vv.x; acc.y += w8 * vv.y;
        acc.z += w8 * vv.z; acc.w += w8 * vv.w;
    }
    *(float4*)(&outp[warp][lane * 4]) = acc;
    __syncthreads();
    if (tid < DKH) {
        float s = 0.0f;
        #pragma unroll
        for (int w = 0; w < 8; w++) s += outp[w][tid];
        g_attn[(size_t)b * DMODEL + h * DKH + tid] = s * inv;
    }
}

// ---------------------------------------------------------------------------
extern "C" void kernel_launch(void* const* d_in, const int* in_sizes, int n_in,
                              void* d_out, int out_size) {
    const float* x  = (const float*)d_in[0];
    const float* kc = (const float*)d_in[1];
    const float* vc = (const float*)d_in[2];
    const float* Wq = (const float*)d_in[3];
    const float* Wk = (const float*)d_in[4];
    const float* Wv = (const float*)d_in[5];
    const float* Wo = (const float*)d_in[6];
    const int* seqp = (const int*)d_in[7];
    float* out = (float*)d_out;

    rope_table_kernel<<<64, 1024>>>();
    split_kernel<<<512, 256>>>(x);
    mma_gemm_kernel<<<dim3(32, KSPLIT, 3), 256>>>(Wq, Wk, Wv);
    reduce_kernel<<<384, 256>>>(nullptr, 3);            // -> g_proj [Q,K,V]
    attn_kernel<<<NB * NH, 256>>>(kc, vc, seqp);
    split_kernel<<<512, 256>>>(nullptr);                // split g_attn
    mma_gemm_kernel<<<dim3(32, KSPLIT, 1), 256>>>(Wo, Wo, Wo);
    reduce_kernel<<<128, 256>>>(out, 1);                // -> d_out
}

// round 10
// speedup vs baseline: 2.2666x; 1.0831x over previous
#include <cuda_runtime.h>
#include <math.h>

#define NB 32
#define NH 32
#define DMODEL 4096
#define DKH 128
#define SINKC 4
#define WINDOWC 1020
#define MAXC (SINKC + WINDOWC)   /* 1024 */
#define KSPLIT 8
#define KCHUNK (DMODEL / KSPLIT) /* 512 */
#define KT 32                    /* k-tile staged in smem */

// Scratch (device globals: no allocation allowed)
__device__ float  g_proj[3 * NB * DMODEL];          // Q, K, V projections
__device__ float  g_attn[NB * DMODEL];              // attention output pre-W_O
__device__ float  g_cos[MAXC * 64];
__device__ float  g_sin[MAXC * 64];
__device__ float2 g_xs[NB * DMODEL];                // split activations (hi,lo)
__device__ float  g_part[3 * KSPLIT * NB * DMODEL]; // GEMM K-split partials (12.6 MB)

// ---------------------------------------------------------------------------
__device__ __forceinline__ unsigned tf32_rna(float x) {
    unsigned r;
    asm("cvt.rna.tf32.f32 %0, %1;" : "=r"(r) : "f"(x));
    return r;
}

__device__ __forceinline__ void mma_tf32(float& d0, float& d1, float& d2, float& d3,
                                         unsigned a0, unsigned a1, unsigned a2, unsigned a3,
                                         unsigned b0, unsigned b1) {
    asm("mma.sync.aligned.m16n8k8.row.col.f32.tf32.tf32.f32 "
        "{%0,%1,%2,%3}, {%4,%5,%6,%7}, {%8,%9}, {%0,%1,%2,%3};"
        : "+f"(d0), "+f"(d1), "+f"(d2), "+f"(d3)
        : "r"(a0), "r"(a1), "r"(a2), "r"(a3), "r"(b0), "r"(b1));
}

// ---------------------------------------------------------------------------
// RoPE tables: cos/sin(pos * theta_j), theta_j = 10000^(-j/64), fp32 like ref
// ---------------------------------------------------------------------------
__global__ void rope_table_kernel() {
    int i = blockIdx.x * blockDim.x + threadIdx.x;   // 0 .. MAXC*64-1
    int pos = i >> 6;
    int j = i & 63;
    float theta = powf(10000.0f, -(float)j / 64.0f);
    float ang = (float)pos * theta;
    float s, c;
    sincosf(ang, &s, &c);
    g_cos[i] = c;
    g_sin[i] = s;
}

// ---------------------------------------------------------------------------
// Split activations into (hi, lo) tf32 pair for 3xTF32. xin == nullptr -> g_attn.
// ---------------------------------------------------------------------------
__global__ void split_kernel(const float* __restrict__ xin) {
    const float* src = xin ? xin : g_attn;
    int i = blockIdx.x * blockDim.x + threadIdx.x;   // 0 .. NB*DMODEL-1
    float v = src[i];
    unsigned hb = tf32_rna(v);
    float hf = __uint_as_float(hb);
    unsigned lb = tf32_rna(v - hf);
    g_xs[i] = make_float2(hf, __uint_as_float(lb));
}

// ---------------------------------------------------------------------------
// tf32 MMA GEMM, smem-staged: part[slot][ks][b][n] = sum_{k chunk} X[b][k]*W[n][k]
// Block = 8 warps, 128 W-rows; warp owns m16. W tile 128x32 staged coalesced in
// smem (row stride 36 floats: A-frag LDS bank-conflict-free). B tile (all 32
// batches x 32 k, hi/lo float2) staged ONCE per block (stride 36 float2:
// conflict-free per half-warp). 3xTF32: D += Ah*Bh + Ah*Bl + Al*Bh.
// grid = (32 m-blocks, KSPLIT, nslots).
// ---------------------------------------------------------------------------
__global__ void mma_gemm_kernel(const float* __restrict__ Wa,
                                const float* __restrict__ Wb,
                                const float* __restrict__ Wc) {
    __shared__ float  sw[128 * 36];
    __shared__ float2 sb[32 * 36];

    int slot = blockIdx.z;
    const float* W = (slot == 0) ? Wa : (slot == 1) ? Wb : Wc;
    int warp = threadIdx.x >> 5;
    int lane = threadIdx.x & 31;
    int r = lane >> 2;          // groupID
    int c = lane & 3;           // threadID_in_group
    int rowbase = blockIdx.x * 128;
    int kb = blockIdx.y * KCHUNK;

    float d[4][4];
    #pragma unroll
    for (int t = 0; t < 4; t++)
        d[t][0] = d[t][1] = d[t][2] = d[t][3] = 0.0f;

    for (int kt = kb; kt < kb + KCHUNK; kt += KT) {
        __syncthreads();
        // W tile: 128 rows x 32 cols = 1024 float4, 4 per thread, coalesced.
        #pragma unroll
        for (int i = 0; i < 4; i++) {
            int idx = i * 256 + threadIdx.x;
            int row = idx >> 3;
            int c4 = (idx & 7) << 2;
            *(float4*)(sw + row * 36 + c4) =
                *(const float4*)(W + (size_t)(rowbase + row) * DMODEL + kt + c4);
        }
        // B tile: 32 batches x 32 k of float2 = 512 float4, 2 per thread.
        #pragma unroll
        for (int i = 0; i < 2; i++) {
            int idx = i * 256 + threadIdx.x;
            int bb = idx >> 4;
            int c4 = idx & 15;            // float4 (= 2 k) index within row
            *(float4*)(&sb[bb * 36 + c4 * 2]) =
                ((const float4*)g_xs)[(size_t)bb * (DMODEL / 2) + (kt >> 1) + c4];
        }
        __syncthreads();

        #pragma unroll
        for (int ko = 0; ko < KT; ko += 8) {
            const float* wrow = sw + (warp * 16 + r) * 36 + ko + c;
            float wa0 = wrow[0];
            float wa1 = wrow[8 * 36];
            float wa2 = wrow[4];
            float wa3 = wrow[8 * 36 + 4];
            unsigned ah0 = tf32_rna(wa0), ah1 = tf32_rna(wa1);
            unsigned ah2 = tf32_rna(wa2), ah3 = tf32_rna(wa3);
            unsigned al0 = tf32_rna(wa0 - __uint_as_float(ah0));
            unsigned al1 = tf32_rna(wa1 - __uint_as_float(ah1));
            unsigned al2 = tf32_rna(wa2 - __uint_as_float(ah2));
            unsigned al3 = tf32_rna(wa3 - __uint_as_float(ah3));

            #pragma unroll
            for (int t = 0; t < 4; t++) {
                float2 xb0 = sb[(t * 8 + r) * 36 + ko + c];
                float2 xb1 = sb[(t * 8 + r) * 36 + ko + c + 4];
                unsigned bh0 = __float_as_uint(xb0.x), bh1 = __float_as_uint(xb1.x);
                unsigned bl0 = __float_as_uint(xb0.y), bl1 = __float_as_uint(xb1.y);
                mma_tf32(d[t][0], d[t][1], d[t][2], d[t][3], ah0, ah1, ah2, ah3, bl0, bl1);
                mma_tf32(d[t][0], d[t][1], d[t][2], d[t][3], al0, al1, al2, al3, bh0, bh1);
                mma_tf32(d[t][0], d[t][1], d[t][2], d[t][3], ah0, ah1, ah2, ah3, bh0, bh1);
            }
        }
    }

    // c-fragment (m16n8): d0 -> (row n0+r, batch bt+2c); d1 -> batch+1; d2/d3 -> row+8.
    int n0 = rowbase + warp * 16;
    float* pp = g_part + (size_t)(slot * KSPLIT + blockIdx.y) * NB * DMODEL;
    #pragma unroll
    for (int t = 0; t < 4; t++) {
        int bt = t * 8;
        pp[(size_t)(bt + 2 * c)     * DMODEL + n0 + r]     = d[t][0];
        pp[(size_t)(bt + 2 * c + 1) * DMODEL + n0 + r]     = d[t][1];
        pp[(size_t)(bt + 2 * c)     * DMODEL + n0 + r + 8] = d[t][2];
        pp[(size_t)(bt + 2 * c + 1) * DMODEL + n0 + r + 8] = d[t][3];
    }
}

// ---------------------------------------------------------------------------
// Reduce KSPLIT partials. dst == nullptr -> g_proj. Layout [slot][b][n].
// ---------------------------------------------------------------------------
__global__ void reduce_kernel(float* __restrict__ dstp, int nslots) {
    float* dst = dstp ? dstp : g_proj;
    int i = blockIdx.x * blockDim.x + threadIdx.x;   // over nslots*NB*DMODEL/4
    int per_slot = NB * (DMODEL / 4);
    if (i >= nslots * per_slot) return;
    int slot = i / per_slot;
    int rem = i - slot * per_slot;
    const float4* src = (const float4*)g_part + (size_t)slot * KSPLIT * per_slot + rem;
    float4 s = make_float4(0.f, 0.f, 0.f, 0.f);
    #pragma unroll
    for (int k = 0; k < KSPLIT; k++) {
        float4 v = src[(size_t)k * per_slot];
        s.x += v.x; s.y += v.y; s.z += v.z; s.w += v.w;
    }
    ((float4*)dst)[i] = s;
}

// ---------------------------------------------------------------------------
// Attention: one block per (b,h). Warp-per-position (2 in flight), float4
// lanes over DK. Caches NOT mutated: active pos p maps to cache row c(p);
// p = L-1 reads the freshly projected K_new / V_new. RoPE flip pair via
// shfl_xor(16).
// ---------------------------------------------------------------------------
__device__ __forceinline__ int cache_row(int p, bool full, int ins, int part2) {
    if (!full || p < SINKC) return p;
    return (p < SINKC + part2) ? (ins + 1 + (p - SINKC))
                               : (SINKC + (p - SINKC - part2));
}

__global__ void attn_kernel(const float* __restrict__ kcache,
                            const float* __restrict__ vcache,
                            const int* __restrict__ seqp) {
    __shared__ float q_rot[DKH];
    __shared__ float scores[MAXC];
    __shared__ float outp[8][DKH];
    __shared__ float red[8];

    int bh = blockIdx.x;
    int b = bh >> 5;
    int h = bh & 31;
    int tid = threadIdx.x, warp = tid >> 5, lane = tid & 31;

    int seq = *seqp;
    int L, ins, part2;
    bool full;
    if (seq < MAXC) { L = seq + 1; ins = seq; part2 = 0; full = false; }
    else { L = MAXC; ins = SINKC + (seq - SINKC) % WINDOWC; part2 = MAXC - (ins + 1); full = true; }

    const float* qsrc = g_proj + ((size_t)b * DMODEL + h * DKH);
    if (tid < DKH) {
        float qv = qsrc[tid];
        float pn = qsrc[tid ^ 64];
        int j = tid & 63;
        float c = g_cos[(L - 1) * 64 + j];
        float s = g_sin[(L - 1) * 64 + j];
        float flip = (tid < 64) ? -pn : pn;
        q_rot[tid] = qv * c + flip * s;
    }
    __syncthreads();

    float4 qf = *(const float4*)(q_rot + lane * 4);
    const float4* kbase = (const float4*)(kcache + (size_t)bh * MAXC * DKH);
    const float4* vbase = (const float4*)(vcache + (size_t)bh * MAXC * DKH);
    const float4* knew  = (const float4*)(g_proj + (size_t)NB * DMODEL + (size_t)b * DMODEL + h * DKH);
    const float4* vnew  = (const float4*)(g_proj + 2 * (size_t)NB * DMODEL + (size_t)b * DMODEL + h * DKH);
    int j4 = (lane & 15) << 2;
    float sgn = (lane < 16) ? -1.0f : 1.0f;

    // ---- pass 1: scores; two positions in flight per warp ----
    for (int p = warp; p < L; p += 16) {
        int pB = p + 8;
        bool hasB = (pB < L);                 // warp-uniform
        int cA = cache_row(p, full, ins, part2);
        const float4* krA = (p == L - 1) ? knew : (kbase + (size_t)cA * (DKH / 4));
        float4 kvA = krA[lane];
        float4 kvB = make_float4(0.f, 0.f, 0.f, 0.f);
        if (hasB) {
            int cB = cache_row(pB, full, ins, part2);
            const float4* krB = (pB == L - 1) ? knew : (kbase + (size_t)cB * (DKH / 4));
            kvB = krB[lane];
        }
        float4 csA = *(const float4*)(g_cos + p * 64 + j4);
        float4 snA = *(const float4*)(g_sin + p * 64 + j4);
        float4 csB = hasB ? *(const float4*)(g_cos + pB * 64 + j4) : csA;
        float4 snB = hasB ? *(const float4*)(g_sin + pB * 64 + j4) : snA;

        float4 pvA, pvB;
        pvA.x = __shfl_xor_sync(0xffffffffu, kvA.x, 16);
        pvB.x = __shfl_xor_sync(0xffffffffu, kvB.x, 16);
        pvA.y = __shfl_xor_sync(0xffffffffu, kvA.y, 16);
        pvB.y = __shfl_xor_sync(0xffffffffu, kvB.y, 16);
        pvA.z = __shfl_xor_sync(0xffffffffu, kvA.z, 16);
        pvB.z = __shfl_xor_sync(0xffffffffu, kvB.z, 16);
        pvA.w = __shfl_xor_sync(0xffffffffu, kvA.w, 16);
        pvB.w = __shfl_xor_sync(0xffffffffu, kvB.w, 16);

        float dA = (kvA.x * csA.x + sgn * pvA.x * snA.x) * qf.x
                 + (kvA.y * csA.y + sgn * pvA.y * snA.y) * qf.y
                 + (kvA.z * csA.z + sgn * pvA.z * snA.z) * qf.z
                 + (kvA.w * csA.w + sgn * pvA.w * snA.w) * qf.w;
        float dB = (kvB.x * csB.x + sgn * pvB.x * snB.x) * qf.x
                 + (kvB.y * csB.y + sgn * pvB.y * snB.y) * qf.y
                 + (kvB.z * csB.z + sgn * pvB.z * snB.z) * qf.z
                 + (kvB.w * csB.w + sgn * pvB.w * snB.w) * qf.w;
        #pragma unroll
        for (int o = 16; o > 0; o >>= 1) {
            dA += __shfl_xor_sync(0xffffffffu, dA, o);
            dB += __shfl_xor_sync(0xffffffffu, dB, o);
        }
        if (lane == 0) {
            scores[p] = dA * 0.08838834764831845f;     // 1/sqrt(128)
            if (hasB) scores[pB] = dB * 0.08838834764831845f;
        }
    }
    __syncthreads();

    // ---- softmax ----
    float m = -1e30f;
    for (int p = tid; p < L; p += 256) m = fmaxf(m, scores[p]);
    #pragma unroll
    for (int o = 16; o > 0; o >>= 1) m = fmaxf(m, __shfl_xor_sync(0xffffffffu, m, o));
    if (lane == 0) red[warp] = m;
    __syncthreads();
    m = red[0];
    #pragma unroll
    for (int w = 1; w < 8; w++) m = fmaxf(m, red[w]);

    float lsum = 0.0f;
    for (int p = tid; p < L; p += 256) {
        float e = __expf(scores[p] - m);
        scores[p] = e;
        lsum += e;
    }
    #pragma unroll
    for (int o = 16; o > 0; o >>= 1) lsum += __shfl_xor_sync(0xffffffffu, lsum, o);
    __syncthreads();                 // all reads of red (max) done
    if (lane == 0) red[warp] = lsum;
    __syncthreads();
    float S = 0.0f;
    #pragma unroll
    for (int w = 0; w < 8; w++) S += red[w];
    float inv = 1.0f / S;

    // ---- pass 2: out = attn @ V ----
    float4 acc = make_float4(0.f, 0.f, 0.f, 0.f);
    for (int p = warp; p < L; p += 8) {
        int c = cache_row(p, full, ins, part2);
        const float4* vrow = (p == L - 1) ? vnew : (vbase + (size_t)c * (DKH / 4));
        float w8 = scores[p];
        float4 vv = vrow[lane];
        acc.x += w8 * vv.x; acc.y += w8 * vv.y;
        acc.z += w8 * vv.z; acc.w += w8 * vv.w;
    }
    *(float4*)(&outp[warp][lane * 4]) = acc;
    __syncthreads();
    if (tid < DKH) {
        float s = 0.0f;
        #pragma unroll
        for (int w = 0; w < 8; w++) s += outp[w][tid];
        g_attn[(size_t)b * DMODEL + h * DKH + tid] = s * inv;
    }
}

// ---------------------------------------------------------------------------
extern "C" void kernel_launch(void* const* d_in, const int* in_sizes, int n_in,
                              void* d_out, int out_size) {
    const float* x  = (const float*)d_in[0];
    const float* kc = (const float*)d_in[1];
    const float* vc = (const float*)d_in[2];
    const float* Wq = (const float*)d_in[3];
    const float* Wk = (const float*)d_in[4];
    const float* Wv = (const float*)d_in[5];
    const float* Wo = (const float*)d_in[6];
    const int* seqp = (const int*)d_in[7];
    float* out = (float*)d_out;

    rope_table_kernel<<<64, 1024>>>();
    split_kernel<<<512, 256>>>(x);
    mma_gemm_kernel<<<dim3(32, KSPLIT, 3), 256>>>(Wq, Wk, Wv);
    reduce_kernel<<<384, 256>>>(nullptr, 3);            // -> g_proj [Q,K,V]
    attn_kernel<<<NB * NH, 256>>>(kc, vc, seqp);
    split_kernel<<<512, 256>>>(nullptr);                // split g_attn
    mma_gemm_kernel<<<dim3(32, KSPLIT, 1), 256>>>(Wo, Wo, Wo);
    reduce_kernel<<<128, 256>>>(out, 1);                // -> d_out
}

// round 12
// speedup vs baseline: 2.3109x; 1.0195x over previous
#include <cuda_runtime.h>
#include <math.h>

#define NB 32
#define NH 32
#define DMODEL 4096
#define DKH 128
#define SINKC 4
#define WINDOWC 1020
#define MAXC (SINKC + WINDOWC)   /* 1024 */
#define KT 32                    /* k-tile staged in smem */

// Scratch (device globals: no allocation allowed)
__device__ float  g_proj[3 * NB * DMODEL];          // Q, K, V projections
__device__ float  g_cos[MAXC * 64];
__device__ float  g_sin[MAXC * 64];
__device__ float2 g_xs[NB * DMODEL];                // split activations (hi,lo)
__device__ float  g_part[24 * NB * DMODEL];         // GEMM K-split partials

// ---------------------------------------------------------------------------
__device__ __forceinline__ unsigned tf32_rna(float x) {
    unsigned r;
    asm("cvt.rna.tf32.f32 %0, %1;" : "=r"(r) : "f"(x));
    return r;
}

__device__ __forceinline__ void mma_tf32(float& d0, float& d1, float& d2, float& d3,
                                         unsigned a0, unsigned a1, unsigned a2, unsigned a3,
                                         unsigned b0, unsigned b1) {
    asm("mma.sync.aligned.m16n8k8.row.col.f32.tf32.tf32.f32 "
        "{%0,%1,%2,%3}, {%4,%5,%6,%7}, {%8,%9}, {%0,%1,%2,%3};"
        : "+f"(d0), "+f"(d1), "+f"(d2), "+f"(d3)
        : "r"(a0), "r"(a1), "r"(a2), "r"(a3), "r"(b0), "r"(b1));
}

__device__ __forceinline__ void cp16(void* smem_dst, const void* gsrc) {
    unsigned d = (unsigned)__cvta_generic_to_shared(smem_dst);
    asm volatile("cp.async.cg.shared.global [%0], [%1], 16;" :: "r"(d), "l"(gsrc));
}
#define CP_COMMIT() asm volatile("cp.async.commit_group;")
#define CP_WAIT1()  asm volatile("cp.async.wait_group 1;")
#define CP_WAIT0()  asm volatile("cp.async.wait_group 0;")

// ---------------------------------------------------------------------------
// RoPE tables: cos/sin(pos * theta_j), theta_j = 10000^(-j/64), fp32 like ref
// ---------------------------------------------------------------------------
__global__ void rope_table_kernel() {
    int i = blockIdx.x * blockDim.x + threadIdx.x;   // 0 .. MAXC*64-1
    int pos = i >> 6;
    int j = i & 63;
    float theta = powf(10000.0f, -(float)j / 64.0f);
    float ang = (float)pos * theta;
    float s, c;
    sincosf(ang, &s, &c);
    g_cos[i] = c;
    g_sin[i] = s;
}

// ---------------------------------------------------------------------------
// Split activations into (hi, lo) tf32 pair for 3xTF32.
// ---------------------------------------------------------------------------
__global__ void split_kernel(const float* __restrict__ src) {
    int i = blockIdx.x * blockDim.x + threadIdx.x;   // 0 .. NB*DMODEL-1
    float v = src[i];
    unsigned hb = tf32_rna(v);
    float hf = __uint_as_float(hb);
    unsigned lb = tf32_rna(v - hf);
    g_xs[i] = make_float2(hf, __uint_as_float(lb));
}

// ---------------------------------------------------------------------------
// tf32 MMA GEMM, cp.async double-buffered:
//   part[slot][ks][b][n] = sum_{k in chunk} X[b][k] * W[n][k]
// Block = 8 warps, 128 W-rows; warp owns m16. W tile 128x32 (stride 36: A-frag
// LDS conflict-free), B tile 32 batches x 32 k hi/lo float2 (stride 36).
// Tile t+1 streams via cp.async while tile t computes.
// 3xTF32: D += Ah*Bh + Ah*Bl + Al*Bh. grid = (32, ksplit, nslots).
// ---------------------------------------------------------------------------
__global__ void mma_gemm_kernel(const float* __restrict__ Wa,
                                const float* __restrict__ Wb,
                                const float* __restrict__ Wc,
                                int ksplit) {
    __shared__ float  sw[2][128 * 36];
    __shared__ float2 sb[2][32 * 36];

    int slot = blockIdx.z;
    const float* W = (slot == 0) ? Wa : (slot == 1) ? Wb : Wc;
    int tid = threadIdx.x;
    int warp = tid >> 5;
    int lane = tid & 31;
    int r = lane >> 2;          // groupID
    int c = lane & 3;           // threadID_in_group
    int rowbase = blockIdx.x * 128;
    int kchunk = DMODEL / ksplit;
    int ntiles = kchunk / KT;
    int kb = blockIdx.y * kchunk;

    // Per-thread staging coordinates (fixed across tiles)
    int wrow0 = tid >> 3;                 // +32 per i; 4 W cp16s
    int wc4   = (tid & 7) << 2;
    int bb0   = tid >> 4;                 // +16 per i; 2 B cp16s
    int bc4   = tid & 15;

    float d[4][4];
    #pragma unroll
    for (int t = 0; t < 4; t++)
        d[t][0] = d[t][1] = d[t][2] = d[t][3] = 0.0f;

    // Prefetch tile 0 into stage 0
    {
        int kt = kb;
        #pragma unroll
        for (int i = 0; i < 4; i++) {
            int row = wrow0 + i * 32;
            cp16(&sw[0][row * 36 + wc4],
                 W + (size_t)(rowbase + row) * DMODEL + kt + wc4);
        }
        #pragma unroll
        for (int i = 0; i < 2; i++) {
            int bbv = bb0 + i * 16;
            cp16(&sb[0][bbv * 36 + bc4 * 2],
                 (const float4*)g_xs + (size_t)bbv * (DMODEL / 2) + (kt >> 1) + bc4);
        }
        CP_COMMIT();
    }

    for (int t = 0; t < ntiles; t++) {
        int st = t & 1;
        if (t + 1 < ntiles) {
            int kt = kb + (t + 1) * KT;
            int ns = (t + 1) & 1;
            #pragma unroll
            for (int i = 0; i < 4; i++) {
                int row = wrow0 + i * 32;
                cp16(&sw[ns][row * 36 + wc4],
                     W + (size_t)(rowbase + row) * DMODEL + kt + wc4);
            }
            #pragma unroll
            for (int i = 0; i < 2; i++) {
                int bbv = bb0 + i * 16;
                cp16(&sb[ns][bbv * 36 + bc4 * 2],
                     (const float4*)g_xs + (size_t)bbv * (DMODEL / 2) + (kt >> 1) + bc4);
            }
            CP_COMMIT();
            CP_WAIT1();          // tile t complete; t+1 still in flight
        } else {
            CP_WAIT0();
        }
        __syncthreads();

        const float*  swp = sw[st];
        const float2* sbp = sb[st];
        #pragma unroll
        for (int ko = 0; ko < KT; ko += 8) {
            const float* wrow = swp + (warp * 16 + r) * 36 + ko + c;
            float wa0 = wrow[0];
            float wa1 = wrow[8 * 36];
            float wa2 = wrow[4];
            float wa3 = wrow[8 * 36 + 4];
            unsigned ah0 = tf32_rna(wa0), ah1 = tf32_rna(wa1);
            unsigned ah2 = tf32_rna(wa2), ah3 = tf32_rna(wa3);
            unsigned al0 = tf32_rna(wa0 - __uint_as_float(ah0));
            unsigned al1 = tf32_rna(wa1 - __uint_as_float(ah1));
            unsigned al2 = tf32_rna(wa2 - __uint_as_float(ah2));
            unsigned al3 = tf32_rna(wa3 - __uint_as_float(ah3));

            #pragma unroll
            for (int tb = 0; tb < 4; tb++) {
                float2 xb0 = sbp[(tb * 8 + r) * 36 + ko + c];
                float2 xb1 = sbp[(tb * 8 + r) * 36 + ko + c + 4];
                unsigned bh0 = __float_as_uint(xb0.x), bh1 = __float_as_uint(xb1.x);
                unsigned bl0 = __float_as_uint(xb0.y), bl1 = __float_as_uint(xb1.y);
                mma_tf32(d[tb][0], d[tb][1], d[tb][2], d[tb][3], ah0, ah1, ah2, ah3, bl0, bl1);
                mma_tf32(d[tb][0], d[tb][1], d[tb][2], d[tb][3], al0, al1, al2, al3, bh0, bh1);
                mma_tf32(d[tb][0], d[tb][1], d[tb][2], d[tb][3], ah0, ah1, ah2, ah3, bh0, bh1);
            }
        }
        __syncthreads();
    }

    // c-fragment (m16n8): d0 -> (row n0+r, batch bt+2c); d1 -> batch+1; d2/d3 -> row+8.
    int n0 = rowbase + warp * 16;
    float* pp = g_part + (size_t)(slot * ksplit + blockIdx.y) * NB * DMODEL;
    #pragma unroll
    for (int t = 0; t < 4; t++) {
        int bt = t * 8;
        pp[(size_t)(bt + 2 * c)     * DMODEL + n0 + r]     = d[t][0];
        pp[(size_t)(bt + 2 * c + 1) * DMODEL + n0 + r]     = d[t][1];
        pp[(size_t)(bt + 2 * c)     * DMODEL + n0 + r + 8] = d[t][2];
        pp[(size_t)(bt + 2 * c + 1) * DMODEL + n0 + r + 8] = d[t][3];
    }
}

// ---------------------------------------------------------------------------
// Reduce ksplit partials. dst == nullptr -> g_proj. Layout [slot][b][n].
// ---------------------------------------------------------------------------
__global__ void reduce_kernel(float* __restrict__ dstp, int nslots, int ksplit) {
    float* dst = dstp ? dstp : g_proj;
    int i = blockIdx.x * blockDim.x + threadIdx.x;   // over nslots*NB*DMODEL/4
    int per_slot = NB * (DMODEL / 4);
    if (i >= nslots * per_slot) return;
    int slot = i / per_slot;
    int rem = i - slot * per_slot;
    const float4* src = (const float4*)g_part + (size_t)slot * ksplit * per_slot + rem;
    float4 s = make_float4(0.f, 0.f, 0.f, 0.f);
    for (int k = 0; k < ksplit; k++) {
        float4 v = src[(size_t)k * per_slot];
        s.x += v.x; s.y += v.y; s.z += v.z; s.w += v.w;
    }
    ((float4*)dst)[i] = s;
}

// ---------------------------------------------------------------------------
// Attention: one block per (b,h). Warp-per-position (2 in flight in both
// passes), float4 lanes over DK. Caches NOT mutated: active pos p maps to
// cache row c(p); p = L-1 reads the freshly projected K_new / V_new.
// Epilogue fuses the tf32 hi/lo split, writing g_xs for the W_O GEMM.
// ---------------------------------------------------------------------------
__device__ __forceinline__ int cache_row(int p, bool full, int ins, int part2) {
    if (!full || p < SINKC) return p;
    return (p < SINKC + part2) ? (ins + 1 + (p - SINKC))
                               : (SINKC + (p - SINKC - part2));
}

__global__ void attn_kernel(const float* __restrict__ kcache,
                            const float* __restrict__ vcache,
                            const int* __restrict__ seqp) {
    __shared__ float q_rot[DKH];
    __shared__ float scores[MAXC];
    __shared__ float outp[8][DKH];
    __shared__ float red[8];

    int bh = blockIdx.x;
    int b = bh >> 5;
    int h = bh & 31;
    int tid = threadIdx.x, warp = tid >> 5, lane = tid & 31;

    int seq = *seqp;
    int L, ins, part2;
    bool full;
    if (seq < MAXC) { L = seq + 1; ins = seq; part2 = 0; full = false; }
    else { L = MAXC; ins = SINKC + (seq - SINKC) % WINDOWC; part2 = MAXC - (ins + 1); full = true; }

    const float* qsrc = g_proj + ((size_t)b * DMODEL + h * DKH);
    if (tid < DKH) {
        float qv = qsrc[tid];
        float pn = qsrc[tid ^ 64];
        int j = tid & 63;
        float c = g_cos[(L - 1) * 64 + j];
        float s = g_sin[(L - 1) * 64 + j];
        float flip = (tid < 64) ? -pn : pn;
        q_rot[tid] = qv * c + flip * s;
    }
    __syncthreads();

    float4 qf = *(const float4*)(q_rot + lane * 4);
    const float4* kbase = (const float4*)(kcache + (size_t)bh * MAXC * DKH);
    const float4* vbase = (const float4*)(vcache + (size_t)bh * MAXC * DKH);
    const float4* knew  = (const float4*)(g_proj + (size_t)NB * DMODEL + (size_t)b * DMODEL + h * DKH);
    const float4* vnew  = (const float4*)(g_proj + 2 * (size_t)NB * DMODEL + (size_t)b * DMODEL + h * DKH);
    int j4 = (lane & 15) << 2;
    float sgn = (lane < 16) ? -1.0f : 1.0f;

    // ---- pass 1: scores; two positions in flight per warp ----
    for (int p = warp; p < L; p += 16) {
        int pB = p + 8;
        bool hasB = (pB < L);                 // warp-uniform
        int cA = cache_row(p, full, ins, part2);
        const float4* krA = (p == L - 1) ? knew : (kbase + (size_t)cA * (DKH / 4));
        float4 kvA = krA[lane];
        float4 kvB = make_float4(0.f, 0.f, 0.f, 0.f);
        if (hasB) {
            int cB = cache_row(pB, full, ins, part2);
            const float4* krB = (pB == L - 1) ? knew : (kbase + (size_t)cB * (DKH / 4));
            kvB = krB[lane];
        }
        float4 csA = *(const float4*)(g_cos + p * 64 + j4);
        float4 snA = *(const float4*)(g_sin + p * 64 + j4);
        float4 csB = hasB ? *(const float4*)(g_cos + pB * 64 + j4) : csA;
        float4 snB = hasB ? *(const float4*)(g_sin + pB * 64 + j4) : snA;

        float4 pvA, pvB;
        pvA.x = __shfl_xor_sync(0xffffffffu, kvA.x, 16);
        pvB.x = __shfl_xor_sync(0xffffffffu, kvB.x, 16);
        pvA.y = __shfl_xor_sync(0xffffffffu, kvA.y, 16);
        pvB.y = __shfl_xor_sync(0xffffffffu, kvB.y, 16);
        pvA.z = __shfl_xor_sync(0xffffffffu, kvA.z, 16);
        pvB.z = __shfl_xor_sync(0xffffffffu, kvB.z, 16);
        pvA.w = __shfl_xor_sync(0xffffffffu, kvA.w, 16);
        pvB.w = __shfl_xor_sync(0xffffffffu, kvB.w, 16);

        float dA = (kvA.x * csA.x + sgn * pvA.x * snA.x) * qf.x
                 + (kvA.y * csA.y + sgn * pvA.y * snA.y) * qf.y
                 + (kvA.z * csA.z + sgn * pvA.z * snA.z) * qf.z
                 + (kvA.w * csA.w + sgn * pvA.w * snA.w) * qf.w;
        float dB = (kvB.x * csB.x + sgn * pvB.x * snB.x) * qf.x
                 + (kvB.y * csB.y + sgn * pvB.y * snB.y) * qf.y
                 + (kvB.z * csB.z + sgn * pvB.z * snB.z) * qf.z
                 + (kvB.w * csB.w + sgn * pvB.w * snB.w) * qf.w;
        #pragma unroll
        for (int o = 16; o > 0; o >>= 1) {
            dA += __shfl_xor_sync(0xffffffffu, dA, o);
            dB += __shfl_xor_sync(0xffffffffu, dB, o);
        }
        if (lane == 0) {
            scores[p] = dA * 0.08838834764831845f;     // 1/sqrt(128)
            if (hasB) scores[pB] = dB * 0.08838834764831845f;
        }
    }
    __syncthreads();

    // ---- softmax ----
    float m = -1e30f;
    for (int p = tid; p < L; p += 256) m = fmaxf(m, scores[p]);
    #pragma unroll
    for (int o = 16; o > 0; o >>= 1) m = fmaxf(m, __shfl_xor_sync(0xffffffffu, m, o));
    if (lane == 0) red[warp] = m;
    __syncthreads();
    m = red[0];
    #pragma unroll
    for (int w = 1; w < 8; w++) m = fmaxf(m, red[w]);

    float lsum = 0.0f;
    for (int p = tid; p < L; p += 256) {
        float e = __expf(scores[p] - m);
        scores[p] = e;
        lsum += e;
    }
    #pragma unroll
    for (int o = 16; o > 0; o >>= 1) lsum += __shfl_xor_sync(0xffffffffu, lsum, o);
    __syncthreads();                 // all reads of red (max) done
    if (lane == 0) red[warp] = lsum;
    __syncthreads();
    float S = 0.0f;
    #pragma unroll
    for (int w = 0; w < 8; w++) S += red[w];
    float inv = 1.0f / S;

    // ---- pass 2: out = attn @ V; two rows in flight per warp ----
    float4 acc = make_float4(0.f, 0.f, 0.f, 0.f);
    for (int p = warp; p < L; p += 16) {
        int pB = p + 8;
        bool hasB = (pB < L);
        int cA = cache_row(p, full, ins, part2);
        const float4* vrA = (p == L - 1) ? vnew : (vbase + (size_t)cA * (DKH / 4));
        float4 vvA = vrA[lane];
        float wA = scores[p];
        float4 vvB = make_float4(0.f, 0.f, 0.f, 0.f);
        float wB = 0.0f;
        if (hasB) {
            int cB = cache_row(pB, full, ins, part2);
            const float4* vrB = (pB == L - 1) ? vnew : (vbase + (size_t)cB * (DKH / 4));
            vvB = vrB[lane];
            wB = scores[pB];
        }
        acc.x += wA * vvA.x + wB * vvB.x;
        acc.y += wA * vvA.y + wB * vvB.y;
        acc.z += wA * vvA.z + wB * vvB.z;
        acc.w += wA * vvA.w + wB * vvB.w;
    }
    *(float4*)(&outp[warp][lane * 4]) = acc;
    __syncthreads();
    if (tid < DKH) {
        float s = 0.0f;
        #pragma unroll
        for (int w = 0; w < 8; w++) s += outp[w][tid];
        float v = s * inv;
        unsigned hb = tf32_rna(v);
        float hf = __uint_as_float(hb);
        unsigned lb = tf32_rna(v - hf);
        g_xs[(size_t)b * DMODEL + h * DKH + tid] = make_float2(hf, __uint_as_float(lb));
    }
}

// ---------------------------------------------------------------------------
extern "C" void kernel_launch(void* const* d_in, const int* in_sizes, int n_in,
                              void* d_out, int out_size) {
    const float* x  = (const float*)d_in[0];
    const float* kc = (const float*)d_in[1];
    const float* vc = (const float*)d_in[2];
    const float* Wq = (const float*)d_in[3];
    const float* Wk = (const float*)d_in[4];
    const float* Wv = (const float*)d_in[5];
    const float* Wo = (const float*)d_in[6];
    const int* seqp = (const int*)d_in[7];
    float* out = (float*)d_out;

    rope_table_kernel<<<64, 1024>>>();
    split_kernel<<<512, 256>>>(x);
    mma_gemm_kernel<<<dim3(32, 8, 3), 256>>>(Wq, Wk, Wv, 8);
    reduce_kernel<<<384, 256>>>(nullptr, 3, 8);          // -> g_proj [Q,K,V]
    attn_kernel<<<NB * NH, 256>>>(kc, vc, seqp);         // also writes g_xs
    mma_gemm_kernel<<<dim3(32, 16, 1), 256>>>(Wo, Wo, Wo, 16);
    reduce_kernel<<<128, 256>>>(out, 1, 16);             // -> d_out
}

// round 13
// speedup vs baseline: 2.3448x; 1.0147x over previous
#include <cuda_runtime.h>
#include <math.h>

#define NB 32
#define NH 32
#define DMODEL 4096
#define DKH 128
#define SINKC 4
#define WINDOWC 1020
#define MAXC (SINKC + WINDOWC)   /* 1024 */
#define KT 32                    /* k-tile staged in smem */
#define QKV_KSPLIT 8

// Scratch (device globals: no allocation allowed)
__device__ float  g_cos[MAXC * 64];
__device__ float  g_sin[MAXC * 64];
__device__ float2 g_xs[NB * DMODEL];                // split activations (hi,lo)
__device__ float  g_part[24 * NB * DMODEL];         // GEMM K-split partials

// ---------------------------------------------------------------------------
__device__ __forceinline__ unsigned tf32_rna(float x) {
    unsigned r;
    asm("cvt.rna.tf32.f32 %0, %1;" : "=r"(r) : "f"(x));
    return r;
}

__device__ __forceinline__ void mma_tf32(float& d0, float& d1, float& d2, float& d3,
                                         unsigned a0, unsigned a1, unsigned a2, unsigned a3,
                                         unsigned b0, unsigned b1) {
    asm("mma.sync.aligned.m16n8k8.row.col.f32.tf32.tf32.f32 "
        "{%0,%1,%2,%3}, {%4,%5,%6,%7}, {%8,%9}, {%0,%1,%2,%3};"
        : "+f"(d0), "+f"(d1), "+f"(d2), "+f"(d3)
        : "r"(a0), "r"(a1), "r"(a2), "r"(a3), "r"(b0), "r"(b1));
}

__device__ __forceinline__ void cp16(void* smem_dst, const void* gsrc) {
    unsigned d = (unsigned)__cvta_generic_to_shared(smem_dst);
    asm volatile("cp.async.cg.shared.global [%0], [%1], 16;" :: "r"(d), "l"(gsrc));
}
#define CP_COMMIT() asm volatile("cp.async.commit_group;")
#define CP_WAIT1()  asm volatile("cp.async.wait_group 1;")
#define CP_WAIT0()  asm volatile("cp.async.wait_group 0;")

// ---------------------------------------------------------------------------
// RoPE tables: cos/sin(pos * theta_j), theta_j = 10000^(-j/64), fp32 like ref
// ---------------------------------------------------------------------------
__global__ void rope_table_kernel() {
    int i = blockIdx.x * blockDim.x + threadIdx.x;   // 0 .. MAXC*64-1
    int pos = i >> 6;
    int j = i & 63;
    float theta = powf(10000.0f, -(float)j / 64.0f);
    float ang = (float)pos * theta;
    float s, c;
    sincosf(ang, &s, &c);
    g_cos[i] = c;
    g_sin[i] = s;
}

// ---------------------------------------------------------------------------
// Split activations into (hi, lo) tf32 pair for 3xTF32.
// ---------------------------------------------------------------------------
__global__ void split_kernel(const float* __restrict__ src) {
    int i = blockIdx.x * blockDim.x + threadIdx.x;   // 0 .. NB*DMODEL-1
    float v = src[i];
    unsigned hb = tf32_rna(v);
    float hf = __uint_as_float(hb);
    unsigned lb = tf32_rna(v - hf);
    g_xs[i] = make_float2(hf, __uint_as_float(lb));
}

// ---------------------------------------------------------------------------
// tf32 MMA GEMM, cp.async double-buffered:
//   part[slot][ks][b][n] = sum_{k in chunk} X[b][k] * W[n][k]
// Block = 8 warps, 128 W-rows; warp owns m16. W tile 128x32 (stride 36: A-frag
// LDS conflict-free), B tile 32 batches x 32 k hi/lo float2 (stride 36).
// Tile t+1 streams via cp.async while tile t computes. A split = LOP3 mask
// (hi, exact tf32) + raw diff (lo, HW-truncated) -- CUTLASS 3xtf32 style.
// 3xTF32: D += Ah*Bh + Ah*Bl + Al*Bh. grid = (32, ksplit, nslots).
// ---------------------------------------------------------------------------
__global__ void mma_gemm_kernel(const float* __restrict__ Wa,
                                const float* __restrict__ Wb,
                                const float* __restrict__ Wc,
                                int ksplit) {
    __shared__ float  sw[2][128 * 36];
    __shared__ float2 sb[2][32 * 36];

    int slot = blockIdx.z;
    const float* W = (slot == 0) ? Wa : (slot == 1) ? Wb : Wc;
    int tid = threadIdx.x;
    int warp = tid >> 5;
    int lane = tid & 31;
    int r = lane >> 2;          // groupID
    int c = lane & 3;           // threadID_in_group
    int rowbase = blockIdx.x * 128;
    int kchunk = DMODEL / ksplit;
    int ntiles = kchunk / KT;
    int kb = blockIdx.y * kchunk;

    // Per-thread staging coordinates (fixed across tiles)
    int wrow0 = tid >> 3;                 // +32 per i; 4 W cp16s
    int wc4   = (tid & 7) << 2;
    int bb0   = tid >> 4;                 // +16 per i; 2 B cp16s
    int bc4   = tid & 15;

    float d[4][4];
    #pragma unroll
    for (int t = 0; t < 4; t++)
        d[t][0] = d[t][1] = d[t][2] = d[t][3] = 0.0f;

    // Prefetch tile 0 into stage 0
    {
        int kt = kb;
        #pragma unroll
        for (int i = 0; i < 4; i++) {
            int row = wrow0 + i * 32;
            cp16(&sw[0][row * 36 + wc4],
                 W + (size_t)(rowbase + row) * DMODEL + kt + wc4);
        }
        #pragma unroll
        for (int i = 0; i < 2; i++) {
            int bbv = bb0 + i * 16;
            cp16(&sb[0][bbv * 36 + bc4 * 2],
                 (const float4*)g_xs + (size_t)bbv * (DMODEL / 2) + (kt >> 1) + bc4);
        }
        CP_COMMIT();
    }

    for (int t = 0; t < ntiles; t++) {
        int st = t & 1;
        if (t + 1 < ntiles) {
            int kt = kb + (t + 1) * KT;
            int ns = (t + 1) & 1;
            #pragma unroll
            for (int i = 0; i < 4; i++) {
                int row = wrow0 + i * 32;
                cp16(&sw[ns][row * 36 + wc4],
                     W + (size_t)(rowbase + row) * DMODEL + kt + wc4);
            }
            #pragma unroll
            for (int i = 0; i < 2; i++) {
                int bbv = bb0 + i * 16;
                cp16(&sb[ns][bbv * 36 + bc4 * 2],
                     (const float4*)g_xs + (size_t)bbv * (DMODEL / 2) + (kt >> 1) + bc4);
            }
            CP_COMMIT();
            CP_WAIT1();          // tile t complete; t+1 still in flight
        } else {
            CP_WAIT0();
        }
        __syncthreads();

        const float*  swp = sw[st];
        const float2* sbp = sb[st];
        #pragma unroll
        for (int ko = 0; ko < KT; ko += 8) {
            const float* wrow = swp + (warp * 16 + r) * 36 + ko + c;
            float wa0 = wrow[0];
            float wa1 = wrow[8 * 36];
            float wa2 = wrow[4];
            float wa3 = wrow[8 * 36 + 4];
            // hi = top 19 bits (exact tf32); lo = exact remainder, fed raw
            // (HMMA ignores mantissa bits below tf32 precision).
            unsigned ah0 = __float_as_uint(wa0) & 0xffffe000u;
            unsigned ah1 = __float_as_uint(wa1) & 0xffffe000u;
            unsigned ah2 = __float_as_uint(wa2) & 0xffffe000u;
            unsigned ah3 = __float_as_uint(wa3) & 0xffffe000u;
            unsigned al0 = __float_as_uint(wa0 - __uint_as_float(ah0));
            unsigned al1 = __float_as_uint(wa1 - __uint_as_float(ah1));
            unsigned al2 = __float_as_uint(wa2 - __uint_as_float(ah2));
            unsigned al3 = __float_as_uint(wa3 - __uint_as_float(ah3));

            #pragma unroll
            for (int tb = 0; tb < 4; tb++) {
                float2 xb0 = sbp[(tb * 8 + r) * 36 + ko + c];
                float2 xb1 = sbp[(tb * 8 + r) * 36 + ko + c + 4];
                unsigned bh0 = __float_as_uint(xb0.x), bh1 = __float_as_uint(xb1.x);
                unsigned bl0 = __float_as_uint(xb0.y), bl1 = __float_as_uint(xb1.y);
                mma_tf32(d[tb][0], d[tb][1], d[tb][2], d[tb][3], ah0, ah1, ah2, ah3, bl0, bl1);
                mma_tf32(d[tb][0], d[tb][1], d[tb][2], d[tb][3], al0, al1, al2, al3, bh0, bh1);
                mma_tf32(d[tb][0], d[tb][1], d[tb][2], d[tb][3], ah0, ah1, ah2, ah3, bh0, bh1);
            }
        }
        __syncthreads();
    }

    // c-fragment (m16n8): d0 -> (row n0+r, batch bt+2c); d1 -> batch+1; d2/d3 -> row+8.
    int n0 = rowbase + warp * 16;
    float* pp = g_part + (size_t)(slot * ksplit + blockIdx.y) * NB * DMODEL;
    #pragma unroll
    for (int t = 0; t < 4; t++) {
        int bt = t * 8;
        pp[(size_t)(bt + 2 * c)     * DMODEL + n0 + r]     = d[t][0];
        pp[(size_t)(bt + 2 * c + 1) * DMODEL + n0 + r]     = d[t][1];
        pp[(size_t)(bt + 2 * c)     * DMODEL + n0 + r + 8] = d[t][2];
        pp[(size_t)(bt + 2 * c + 1) * DMODEL + n0 + r + 8] = d[t][3];
    }
}

// ---------------------------------------------------------------------------
// Reduce ksplit partials (used for W_O only). Layout [ks][b][n], slot 0.
// ---------------------------------------------------------------------------
__global__ void reduce_kernel(float* __restrict__ dst, int ksplit) {
    int i = blockIdx.x * blockDim.x + threadIdx.x;   // over NB*DMODEL/4
    int per_slot = NB * (DMODEL / 4);
    if (i >= per_slot) return;
    const float4* src = (const float4*)g_part + i;
    float4 s = make_float4(0.f, 0.f, 0.f, 0.f);
    for (int k = 0; k < ksplit; k++) {
        float4 v = src[(size_t)k * per_slot];
        s.x += v.x; s.y += v.y; s.z += v.z; s.w += v.w;
    }
    ((float4*)dst)[i] = s;
}

// ---------------------------------------------------------------------------
// Attention: one block per (b,h). Prologue reduces the QKV K-split partials
// for just this block's q / k_new / v_new rows (g_part, 8 partials each).
// Warp-per-position (2 in flight, both passes), float4 lanes over DK.
// Caches NOT mutated: active pos p maps to cache row c(p); p = L-1 reads the
// freshly reduced k_new/v_new in smem. Epilogue fuses the tf32 hi/lo split,
// writing g_xs for the W_O GEMM.
// ---------------------------------------------------------------------------
__device__ __forceinline__ int cache_row(int p, bool full, int ins, int part2) {
    if (!full || p < SINKC) return p;
    return (p < SINKC + part2) ? (ins + 1 + (p - SINKC))
                               : (SINKC + (p - SINKC - part2));
}

__global__ void attn_kernel(const float* __restrict__ kcache,
                            const float* __restrict__ vcache,
                            const int* __restrict__ seqp) {
    __shared__ __align__(16) float q_raw[DKH];
    __shared__ __align__(16) float knew_s[DKH];
    __shared__ __align__(16) float vnew_s[DKH];
    __shared__ float q_rot[DKH];
    __shared__ float scores[MAXC];
    __shared__ float outp[8][DKH];
    __shared__ float red[8];

    int bh = blockIdx.x;
    int b = bh >> 5;
    int h = bh & 31;
    int tid = threadIdx.x, warp = tid >> 5, lane = tid & 31;

    // ---- prologue: reduce QKV partials for this (b,h) ----
    for (int i = tid; i < 3 * DKH; i += 256) {
        int slot = i >> 7;           // 0=q, 1=k_new, 2=v_new
        int d = i & (DKH - 1);
        const float* base = g_part
            + ((size_t)(slot * QKV_KSPLIT) * NB + b) * DMODEL + h * DKH + d;
        float s = 0.0f;
        #pragma unroll
        for (int ks = 0; ks < QKV_KSPLIT; ks++)
            s += base[(size_t)ks * NB * DMODEL];
        if (slot == 0) q_raw[d] = s;
        else if (slot == 1) knew_s[d] = s;
        else vnew_s[d] = s;
    }
    __syncthreads();

    int seq = *seqp;
    int L, ins, part2;
    bool full;
    if (seq < MAXC) { L = seq + 1; ins = seq; part2 = 0; full = false; }
    else { L = MAXC; ins = SINKC + (seq - SINKC) % WINDOWC; part2 = MAXC - (ins + 1); full = true; }

    if (tid < DKH) {
        float qv = q_raw[tid];
        float pn = q_raw[tid ^ 64];
        int j = tid & 63;
        float c = g_cos[(L - 1) * 64 + j];
        float s = g_sin[(L - 1) * 64 + j];
        float flip = (tid < 64) ? -pn : pn;
        q_rot[tid] = qv * c + flip * s;
    }
    __syncthreads();

    float4 qf = *(const float4*)(q_rot + lane * 4);
    const float4* kbase = (const float4*)(kcache + (size_t)bh * MAXC * DKH);
    const float4* vbase = (const float4*)(vcache + (size_t)bh * MAXC * DKH);
    const float4* knew  = (const float4*)knew_s;
    const float4* vnew  = (const float4*)vnew_s;
    int j4 = (lane & 15) << 2;
    float sgn = (lane < 16) ? -1.0f : 1.0f;

    // ---- pass 1: scores; two positions in flight per warp ----
    for (int p = warp; p < L; p += 16) {
        int pB = p + 8;
        bool hasB = (pB < L);                 // warp-uniform
        int cA = cache_row(p, full, ins, part2);
        const float4* krA = (p == L - 1) ? knew : (kbase + (size_t)cA * (DKH / 4));
        float4 kvA = krA[lane];
        float4 kvB = make_float4(0.f, 0.f, 0.f, 0.f);
        if (hasB) {
            int cB = cache_row(pB, full, ins, part2);
            const float4* krB = (pB == L - 1) ? knew : (kbase + (size_t)cB * (DKH / 4));
            kvB = krB[lane];
        }
        float4 csA = *(const float4*)(g_cos + p * 64 + j4);
        float4 snA = *(const float4*)(g_sin + p * 64 + j4);
        float4 csB = hasB ? *(const float4*)(g_cos + pB * 64 + j4) : csA;
        float4 snB = hasB ? *(const float4*)(g_sin + pB * 64 + j4) : snA;

        float4 pvA, pvB;
        pvA.x = __shfl_xor_sync(0xffffffffu, kvA.x, 16);
        pvB.x = __shfl_xor_sync(0xffffffffu, kvB.x, 16);
        pvA.y = __shfl_xor_sync(0xffffffffu, kvA.y, 16);
        pvB.y = __shfl_xor_sync(0xffffffffu, kvB.y, 16);
        pvA.z = __shfl_xor_sync(0xffffffffu, kvA.z, 16);
        pvB.z = __shfl_xor_sync(0xffffffffu, kvB.z, 16);
        pvA.w = __shfl_xor_sync(0xffffffffu, kvA.w, 16);
        pvB.w = __shfl_xor_sync(0xffffffffu, kvB.w, 16);

        float dA = (kvA.x * csA.x + sgn * pvA.x * snA.x) * qf.x
                 + (kvA.y * csA.y + sgn * pvA.y * snA.y) * qf.y
                 + (kvA.z * csA.z + sgn * pvA.z * snA.z) * qf.z
                 + (kvA.w * csA.w + sgn * pvA.w * snA.w) * qf.w;
        float dB = (kvB.x * csB.x + sgn * pvB.x * snB.x) * qf.x
                 + (kvB.y * csB.y + sgn * pvB.y * snB.y) * qf.y
                 + (kvB.z * csB.z + sgn * pvB.z * snB.z) * qf.z
                 + (kvB.w * csB.w + sgn * pvB.w * snB.w) * qf.w;
        #pragma unroll
        for (int o = 16; o > 0; o >>= 1) {
            dA += __shfl_xor_sync(0xffffffffu, dA, o);
            dB += __shfl_xor_sync(0xffffffffu, dB, o);
        }
        if (lane == 0) {
            scores[p] = dA * 0.08838834764831845f;     // 1/sqrt(128)
            if (hasB) scores[pB] = dB * 0.08838834764831845f;
        }
    }
    __syncthreads();

    // ---- softmax ----
    float m = -1e30f;
    for (int p = tid; p < L; p += 256) m = fmaxf(m, scores[p]);
    #pragma unroll
    for (int o = 16; o > 0; o >>= 1) m = fmaxf(m, __shfl_xor_sync(0xffffffffu, m, o));
    if (lane == 0) red[warp] = m;
    __syncthreads();
    m = red[0];
    #pragma unroll
    for (int w = 1; w < 8; w++) m = fmaxf(m, red[w]);

    float lsum = 0.0f;
    for (int p = tid; p < L; p += 256) {
        float e = __expf(scores[p] - m);
        scores[p] = e;
        lsum += e;
    }
    #pragma unroll
    for (int o = 16; o > 0; o >>= 1) lsum += __shfl_xor_sync(0xffffffffu, lsum, o);
    __syncthreads();                 // all reads of red (max) done
    if (lane == 0) red[warp] = lsum;
    __syncthreads();
    float S = 0.0f;
    #pragma unroll
    for (int w = 0; w < 8; w++) S += red[w];
    float inv = 1.0f / S;

    // ---- pass 2: out = attn @ V; two rows in flight per warp ----
    float4 acc = make_float4(0.f, 0.f, 0.f, 0.f);
    for (int p = warp; p < L; p += 16) {
        int pB = p + 8;
        bool hasB = (pB < L);
        int cA = cache_row(p, full, ins, part2);
        const float4* vrA = (p == L - 1) ? vnew : (vbase + (size_t)cA * (DKH / 4));
        float4 vvA = vrA[lane];
        float wA = scores[p];
        float4 vvB = make_float4(0.f, 0.f, 0.f, 0.f);
        float wB = 0.0f;
        if (hasB) {
            int cB = cache_row(pB, full, ins, part2);
            const float4* vrB = (pB == L - 1) ? vnew : (vbase + (size_t)cB * (DKH / 4));
            vvB = vrB[lane];
            wB = scores[pB];
        }
        acc.x += wA * vvA.x + wB * vvB.x;
        acc.y += wA * vvA.y + wB * vvB.y;
        acc.z += wA * vvA.z + wB * vvB.z;
        acc.w += wA * vvA.w + wB * vvB.w;
    }
    *(float4*)(&outp[warp][lane * 4]) = acc;
    __syncthreads();
    if (tid < DKH) {
        float s = 0.0f;
        #pragma unroll
        for (int w = 0; w < 8; w++) s += outp[w][tid];
        float v = s * inv;
        unsigned hb = tf32_rna(v);
        float hf = __uint_as_float(hb);
        unsigned lb = tf32_rna(v - hf);
        g_xs[(size_t)b * DMODEL + h * DKH + tid] = make_float2(hf, __uint_as_float(lb));
    }
}

// ---------------------------------------------------------------------------
extern "C" void kernel_launch(void* const* d_in, const int* in_sizes, int n_in,
                              void* d_out, int out_size) {
    const float* x  = (const float*)d_in[0];
    const float* kc = (const float*)d_in[1];
    const float* vc = (const float*)d_in[2];
    const float* Wq = (const float*)d_in[3];
    const float* Wk = (const float*)d_in[4];
    const float* Wv = (const float*)d_in[5];
    const float* Wo = (const float*)d_in[6];
    const int* seqp = (const int*)d_in[7];
    float* out = (float*)d_out;

    rope_table_kernel<<<64, 1024>>>();                       // launch 0
    split_kernel<<<512, 256>>>(x);                           // launch 1
    mma_gemm_kernel<<<dim3(32, QKV_KSPLIT, 3), 256>>>(Wq, Wk, Wv, QKV_KSPLIT); // 2
    attn_kernel<<<NB * NH, 256>>>(kc, vc, seqp);             // launch 3 (profiled)
    mma_gemm_kernel<<<dim3(32, 16, 1), 256>>>(Wo, Wo, Wo, 16);
    reduce_kernel<<<128, 256>>>(out, 16);                    // -> d_out
}

// round 14
// speedup vs baseline: 2.4480x; 1.0440x over previous
#include <cuda_runtime.h>
#include <math.h>

#define NB 32
#define NH 32
#define DMODEL 4096
#define DKH 128
#define SINKC 4
#define WINDOWC 1020
#define MAXC (SINKC + WINDOWC)   /* 1024 */
#define KT 32                    /* k-tile staged in smem */
#define QKV_KSPLIT 8
#define NSPLIT 4                 /* attention position partitions */
#define PART (MAXC / NSPLIT)     /* 256 positions per partition */

// Scratch (device globals: no allocation allowed)
__device__ float  g_cos[MAXC * 64];
__device__ float  g_sin[MAXC * 64];
__device__ float2 g_xs[NB * DMODEL];                  // split activations (hi,lo)
__device__ float  g_part[24 * NB * DMODEL];           // GEMM K-split partials
__device__ float  g_split[NB * NH * NSPLIT * 132];    // per-partition m,S,acc

// ---------------------------------------------------------------------------
__device__ __forceinline__ unsigned tf32_rna(float x) {
    unsigned r;
    asm("cvt.rna.tf32.f32 %0, %1;" : "=r"(r) : "f"(x));
    return r;
}

__device__ __forceinline__ void mma_tf32(float& d0, float& d1, float& d2, float& d3,
                                         unsigned a0, unsigned a1, unsigned a2, unsigned a3,
                                         unsigned b0, unsigned b1) {
    asm("mma.sync.aligned.m16n8k8.row.col.f32.tf32.tf32.f32 "
        "{%0,%1,%2,%3}, {%4,%5,%6,%7}, {%8,%9}, {%0,%1,%2,%3};"
        : "+f"(d0), "+f"(d1), "+f"(d2), "+f"(d3)
        : "r"(a0), "r"(a1), "r"(a2), "r"(a3), "r"(b0), "r"(b1));
}

__device__ __forceinline__ void cp16(void* smem_dst, const void* gsrc) {
    unsigned d = (unsigned)__cvta_generic_to_shared(smem_dst);
    asm volatile("cp.async.cg.shared.global [%0], [%1], 16;" :: "r"(d), "l"(gsrc));
}
#define CP_COMMIT() asm volatile("cp.async.commit_group;")
#define CP_WAIT1()  asm volatile("cp.async.wait_group 1;")
#define CP_WAIT0()  asm volatile("cp.async.wait_group 0;")

// ---------------------------------------------------------------------------
// RoPE tables: cos/sin(pos * theta_j), theta_j = 10000^(-j/64), fp32 like ref
// ---------------------------------------------------------------------------
__global__ void rope_table_kernel() {
    int i = blockIdx.x * blockDim.x + threadIdx.x;   // 0 .. MAXC*64-1
    int pos = i >> 6;
    int j = i & 63;
    float theta = powf(10000.0f, -(float)j / 64.0f);
    float ang = (float)pos * theta;
    float s, c;
    sincosf(ang, &s, &c);
    g_cos[i] = c;
    g_sin[i] = s;
}

// ---------------------------------------------------------------------------
// Split activations into (hi, lo) tf32 pair for 3xTF32.
// ---------------------------------------------------------------------------
__global__ void split_kernel(const float* __restrict__ src) {
    int i = blockIdx.x * blockDim.x + threadIdx.x;   // 0 .. NB*DMODEL-1
    float v = src[i];
    unsigned hb = tf32_rna(v);
    float hf = __uint_as_float(hb);
    unsigned lb = tf32_rna(v - hf);
    g_xs[i] = make_float2(hf, __uint_as_float(lb));
}

// ---------------------------------------------------------------------------
// tf32 MMA GEMM, cp.async double-buffered (unchanged from R13).
// ---------------------------------------------------------------------------
__global__ void mma_gemm_kernel(const float* __restrict__ Wa,
                                const float* __restrict__ Wb,
                                const float* __restrict__ Wc,
                                int ksplit) {
    __shared__ float  sw[2][128 * 36];
    __shared__ float2 sb[2][32 * 36];

    int slot = blockIdx.z;
    const float* W = (slot == 0) ? Wa : (slot == 1) ? Wb : Wc;
    int tid = threadIdx.x;
    int warp = tid >> 5;
    int lane = tid & 31;
    int r = lane >> 2;
    int c = lane & 3;
    int rowbase = blockIdx.x * 128;
    int kchunk = DMODEL / ksplit;
    int ntiles = kchunk / KT;
    int kb = blockIdx.y * kchunk;

    int wrow0 = tid >> 3;
    int wc4   = (tid & 7) << 2;
    int bb0   = tid >> 4;
    int bc4   = tid & 15;

    float d[4][4];
    #pragma unroll
    for (int t = 0; t < 4; t++)
        d[t][0] = d[t][1] = d[t][2] = d[t][3] = 0.0f;

    {
        int kt = kb;
        #pragma unroll
        for (int i = 0; i < 4; i++) {
            int row = wrow0 + i * 32;
            cp16(&sw[0][row * 36 + wc4],
                 W + (size_t)(rowbase + row) * DMODEL + kt + wc4);
        }
        #pragma unroll
        for (int i = 0; i < 2; i++) {
            int bbv = bb0 + i * 16;
            cp16(&sb[0][bbv * 36 + bc4 * 2],
                 (const float4*)g_xs + (size_t)bbv * (DMODEL / 2) + (kt >> 1) + bc4);
        }
        CP_COMMIT();
    }

    for (int t = 0; t < ntiles; t++) {
        int st = t & 1;
        if (t + 1 < ntiles) {
            int kt = kb + (t + 1) * KT;
            int ns = (t + 1) & 1;
            #pragma unroll
            for (int i = 0; i < 4; i++) {
                int row = wrow0 + i * 32;
                cp16(&sw[ns][row * 36 + wc4],
                     W + (size_t)(rowbase + row) * DMODEL + kt + wc4);
            }
            #pragma unroll
            for (int i = 0; i < 2; i++) {
                int bbv = bb0 + i * 16;
                cp16(&sb[ns][bbv * 36 + bc4 * 2],
                     (const float4*)g_xs + (size_t)bbv * (DMODEL / 2) + (kt >> 1) + bc4);
            }
            CP_COMMIT();
            CP_WAIT1();
        } else {
            CP_WAIT0();
        }
        __syncthreads();

        const float*  swp = sw[st];
        const float2* sbp = sb[st];
        #pragma unroll
        for (int ko = 0; ko < KT; ko += 8) {
            const float* wrow = swp + (warp * 16 + r) * 36 + ko + c;
            float wa0 = wrow[0];
            float wa1 = wrow[8 * 36];
            float wa2 = wrow[4];
            float wa3 = wrow[8 * 36 + 4];
            unsigned ah0 = __float_as_uint(wa0) & 0xffffe000u;
            unsigned ah1 = __float_as_uint(wa1) & 0xffffe000u;
            unsigned ah2 = __float_as_uint(wa2) & 0xffffe000u;
            unsigned ah3 = __float_as_uint(wa3) & 0xffffe000u;
            unsigned al0 = __float_as_uint(wa0 - __uint_as_float(ah0));
            unsigned al1 = __float_as_uint(wa1 - __uint_as_float(ah1));
            unsigned al2 = __float_as_uint(wa2 - __uint_as_float(ah2));
            unsigned al3 = __float_as_uint(wa3 - __uint_as_float(ah3));

            #pragma unroll
            for (int tb = 0; tb < 4; tb++) {
                float2 xb0 = sbp[(tb * 8 + r) * 36 + ko + c];
                float2 xb1 = sbp[(tb * 8 + r) * 36 + ko + c + 4];
                unsigned bh0 = __float_as_uint(xb0.x), bh1 = __float_as_uint(xb1.x);
                unsigned bl0 = __float_as_uint(xb0.y), bl1 = __float_as_uint(xb1.y);
                mma_tf32(d[tb][0], d[tb][1], d[tb][2], d[tb][3], ah0, ah1, ah2, ah3, bl0, bl1);
                mma_tf32(d[tb][0], d[tb][1], d[tb][2], d[tb][3], al0, al1, al2, al3, bh0, bh1);
                mma_tf32(d[tb][0], d[tb][1], d[tb][2], d[tb][3], ah0, ah1, ah2, ah3, bh0, bh1);
            }
        }
        __syncthreads();
    }

    int n0 = rowbase + warp * 16;
    float* pp = g_part + (size_t)(slot * ksplit + blockIdx.y) * NB * DMODEL;
    #pragma unroll
    for (int t = 0; t < 4; t++) {
        int bt = t * 8;
        pp[(size_t)(bt + 2 * c)     * DMODEL + n0 + r]     = d[t][0];
        pp[(size_t)(bt + 2 * c + 1) * DMODEL + n0 + r]     = d[t][1];
        pp[(size_t)(bt + 2 * c)     * DMODEL + n0 + r + 8] = d[t][2];
        pp[(size_t)(bt + 2 * c + 1) * DMODEL + n0 + r + 8] = d[t][3];
    }
}

// ---------------------------------------------------------------------------
// Reduce ksplit partials (W_O only). Layout [ks][b][n], slot 0.
// ---------------------------------------------------------------------------
__global__ void reduce_kernel(float* __restrict__ dst, int ksplit) {
    int i = blockIdx.x * blockDim.x + threadIdx.x;
    int per_slot = NB * (DMODEL / 4);
    if (i >= per_slot) return;
    const float4* src = (const float4*)g_part + i;
    float4 s = make_float4(0.f, 0.f, 0.f, 0.f);
    for (int k = 0; k < ksplit; k++) {
        float4 v = src[(size_t)k * per_slot];
        s.x += v.x; s.y += v.y; s.z += v.z; s.w += v.w;
    }
    ((float4*)dst)[i] = s;
}

// ---------------------------------------------------------------------------
// Attention, flash-decode split: grid (NB*NH, NSPLIT). Each block handles
// PART positions of one (b,h) and emits unnormalized (m, S, acc[128]) to
// g_split. Prologue reduces q partials (and k_new/v_new only if this
// partition owns position L-1). Caches NOT mutated; p = L-1 reads the
// freshly reduced k_new/v_new from smem.
// ---------------------------------------------------------------------------
__device__ __forceinline__ int cache_row(int p, bool full, int ins, int part2) {
    if (!full || p < SINKC) return p;
    return (p < SINKC + part2) ? (ins + 1 + (p - SINKC))
                               : (SINKC + (p - SINKC - part2));
}

__global__ void attn_kernel(const float* __restrict__ kcache,
                            const float* __restrict__ vcache,
                            const int* __restrict__ seqp) {
    __shared__ __align__(16) float q_raw[DKH];
    __shared__ __align__(16) float knew_s[DKH];
    __shared__ __align__(16) float vnew_s[DKH];
    __shared__ float q_rot[DKH];
    __shared__ float scores[PART];
    __shared__ float outp[8][DKH];
    __shared__ float red[8];

    int bh = blockIdx.x;
    int sp = blockIdx.y;
    int b = bh >> 5;
    int h = bh & 31;
    int tid = threadIdx.x, warp = tid >> 5, lane = tid & 31;

    int seq = *seqp;
    int L, ins, part2;
    bool full;
    if (seq < MAXC) { L = seq + 1; ins = seq; part2 = 0; full = false; }
    else { L = MAXC; ins = SINKC + (seq - SINKC) % WINDOWC; part2 = MAXC - (ins + 1); full = true; }

    int ps = sp * PART;
    int pe = min(ps + PART, L);
    bool need_new = (L - 1 >= ps) && (L - 1 < ps + PART);

    // ---- prologue: reduce QKV K-split partials for this (b,h) ----
    for (int i = tid; i < 3 * DKH; i += 256) {
        int slot = i >> 7;           // 0=q, 1=k_new, 2=v_new
        if (slot != 0 && !need_new) continue;
        int d = i & (DKH - 1);
        const float* base = g_part
            + ((size_t)(slot * QKV_KSPLIT) * NB + b) * DMODEL + h * DKH + d;
        float s = 0.0f;
        #pragma unroll
        for (int ks = 0; ks < QKV_KSPLIT; ks++)
            s += base[(size_t)ks * NB * DMODEL];
        if (slot == 0) q_raw[d] = s;
        else if (slot == 1) knew_s[d] = s;
        else vnew_s[d] = s;
    }
    __syncthreads();

    if (tid < DKH) {
        float qv = q_raw[tid];
        float pn = q_raw[tid ^ 64];
        int j = tid & 63;
        float c = g_cos[(L - 1) * 64 + j];
        float s = g_sin[(L - 1) * 64 + j];
        float flip = (tid < 64) ? -pn : pn;
        q_rot[tid] = qv * c + flip * s;
    }
    __syncthreads();

    float4 qf = *(const float4*)(q_rot + lane * 4);
    const float4* kbase = (const float4*)(kcache + (size_t)bh * MAXC * DKH);
    const float4* vbase = (const float4*)(vcache + (size_t)bh * MAXC * DKH);
    const float4* knew  = (const float4*)knew_s;
    const float4* vnew  = (const float4*)vnew_s;
    int j4 = (lane & 15) << 2;
    float sgn = (lane < 16) ? -1.0f : 1.0f;

    // ---- pass 1: scores for [ps, pe); two positions in flight per warp ----
    for (int p = ps + warp; p < pe; p += 16) {
        int pB = p + 8;
        bool hasB = (pB < pe);                // warp-uniform
        int cA = cache_row(p, full, ins, part2);
        const float4* krA = (p == L - 1) ? knew : (kbase + (size_t)cA * (DKH / 4));
        float4 kvA = krA[lane];
        float4 kvB = make_float4(0.f, 0.f, 0.f, 0.f);
        if (hasB) {
            int cB = cache_row(pB, full, ins, part2);
            const float4* krB = (pB == L - 1) ? knew : (kbase + (size_t)cB * (DKH / 4));
            kvB = krB[lane];
        }
        float4 csA = *(const float4*)(g_cos + p * 64 + j4);
        float4 snA = *(const float4*)(g_sin + p * 64 + j4);
        float4 csB = hasB ? *(const float4*)(g_cos + pB * 64 + j4) : csA;
        float4 snB = hasB ? *(const float4*)(g_sin + pB * 64 + j4) : snA;

        float4 pvA, pvB;
        pvA.x = __shfl_xor_sync(0xffffffffu, kvA.x, 16);
        pvB.x = __shfl_xor_sync(0xffffffffu, kvB.x, 16);
        pvA.y = __shfl_xor_sync(0xffffffffu, kvA.y, 16);
        pvB.y = __shfl_xor_sync(0xffffffffu, kvB.y, 16);
        pvA.z = __shfl_xor_sync(0xffffffffu, kvA.z, 16);
        pvB.z = __shfl_xor_sync(0xffffffffu, kvB.z, 16);
        pvA.w = __shfl_xor_sync(0xffffffffu, kvA.w, 16);
        pvB.w = __shfl_xor_sync(0xffffffffu, kvB.w, 16);

        float dA = (kvA.x * csA.x + sgn * pvA.x * snA.x) * qf.x
                 + (kvA.y * csA.y + sgn * pvA.y * snA.y) * qf.y
                 + (kvA.z * csA.z + sgn * pvA.z * snA.z) * qf.z
                 + (kvA.w * csA.w + sgn * pvA.w * snA.w) * qf.w;
        float dB = (kvB.x * csB.x + sgn * pvB.x * snB.x) * qf.x
                 + (kvB.y * csB.y + sgn * pvB.y * snB.y) * qf.y
                 + (kvB.z * csB.z + sgn * pvB.z * snB.z) * qf.z
                 + (kvB.w * csB.w + sgn * pvB.w * snB.w) * qf.w;
        #pragma unroll
        for (int o = 16; o > 0; o >>= 1) {
            dA += __shfl_xor_sync(0xffffffffu, dA, o);
            dB += __shfl_xor_sync(0xffffffffu, dB, o);
        }
        if (lane == 0) {
            scores[p - ps] = dA * 0.08838834764831845f;   // 1/sqrt(128)
            if (hasB) scores[pB - ps] = dB * 0.08838834764831845f;
        }
    }
    __syncthreads();

    // ---- partition softmax stats ----
    int n = pe - ps;                         // may be <= 0 (empty partition)
    float m = -1e30f;
    for (int p = tid; p < n; p += 256) m = fmaxf(m, scores[p]);
    #pragma unroll
    for (int o = 16; o > 0; o >>= 1) m = fmaxf(m, __shfl_xor_sync(0xffffffffu, m, o));
    if (lane == 0) red[warp] = m;
    __syncthreads();
    m = red[0];
    #pragma unroll
    for (int w = 1; w < 8; w++) m = fmaxf(m, red[w]);

    float lsum = 0.0f;
    for (int p = tid; p < n; p += 256) {
        float e = __expf(scores[p] - m);
        scores[p] = e;
        lsum += e;
    }
    #pragma unroll
    for (int o = 16; o > 0; o >>= 1) lsum += __shfl_xor_sync(0xffffffffu, lsum, o);
    __syncthreads();                 // reads of red (max) done
    if (lane == 0) red[warp] = lsum;
    __syncthreads();
    float S = 0.0f;
    #pragma unroll
    for (int w = 0; w < 8; w++) S += red[w];

    // ---- pass 2: unnormalized acc over [ps, pe) ----
    float4 acc = make_float4(0.f, 0.f, 0.f, 0.f);
    for (int p = ps + warp; p < pe; p += 16) {
        int pB = p + 8;
        bool hasB = (pB < pe);
        int cA = cache_row(p, full, ins, part2);
        const float4* vrA = (p == L - 1) ? vnew : (vbase + (size_t)cA * (DKH / 4));
        float4 vvA = vrA[lane];
        float wA = scores[p - ps];
        float4 vvB = make_float4(0.f, 0.f, 0.f, 0.f);
        float wB = 0.0f;
        if (hasB) {
            int cB = cache_row(pB, full, ins, part2);
            const float4* vrB = (pB == L - 1) ? vnew : (vbase + (size_t)cB * (DKH / 4));
            vvB = vrB[lane];
            wB = scores[pB - ps];
        }
        acc.x += wA * vvA.x + wB * vvB.x;
        acc.y += wA * vvA.y + wB * vvB.y;
        acc.z += wA * vvA.z + wB * vvB.z;
        acc.w += wA * vvA.w + wB * vvB.w;
    }
    *(float4*)(&outp[warp][lane * 4]) = acc;
    __syncthreads();

    float* dst = g_split + ((size_t)bh * NSPLIT + sp) * 132;
    if (tid < DKH) {
        float s = 0.0f;
        #pragma unroll
        for (int w = 0; w < 8; w++) s += outp[w][tid];
        dst[tid] = s;
    } else if (tid == 128) {
        dst[128] = m;
        dst[129] = S;
    }
}

// ---------------------------------------------------------------------------
// Combine partitions: out = (sum_s w_s acc_s) / (sum_s w_s S_s), w_s=e^{m_s-m}.
// Writes the tf32 hi/lo split activations for the W_O GEMM.
// grid = NB*NH blocks of 128 threads.
// ---------------------------------------------------------------------------
__global__ void combine_kernel() {
    __shared__ float w[NSPLIT];
    __shared__ float Ssh;
    int bh = blockIdx.x;
    int tid = threadIdx.x;
    int b = bh >> 5;
    int h = bh & 31;
    const float* base = g_split + (size_t)bh * NSPLIT * 132;

    if (tid == 0) {
        float ms[NSPLIT], Ss[NSPLIT];
        float m = -1e30f;
        #pragma unroll
        for (int s = 0; s < NSPLIT; s++) {
            ms[s] = base[s * 132 + 128];
            Ss[s] = base[s * 132 + 129];
            m = fmaxf(m, ms[s]);
        }
        float S = 0.0f;
        #pragma unroll
        for (int s = 0; s < NSPLIT; s++) {
            float ws = __expf(ms[s] - m);
            w[s] = ws;
            S += ws * Ss[s];
        }
        Ssh = S;
    }
    __syncthreads();

    float a = 0.0f;
    #pragma unroll
    for (int s = 0; s < NSPLIT; s++) a += w[s] * base[s * 132 + tid];
    float v = a / Ssh;
    unsigned hb = tf32_rna(v);
    float hf = __uint_as_float(hb);
    unsigned lb = tf32_rna(v - hf);
    g_xs[(size_t)b * DMODEL + h * DKH + tid] = make_float2(hf, __uint_as_float(lb));
}

// ---------------------------------------------------------------------------
extern "C" void kernel_launch(void* const* d_in, const int* in_sizes, int n_in,
                              void* d_out, int out_size) {
    const float* x  = (const float*)d_in[0];
    const float* kc = (const float*)d_in[1];
    const float* vc = (const float*)d_in[2];
    const float* Wq = (const float*)d_in[3];
    const float* Wk = (const float*)d_in[4];
    const float* Wv = (const float*)d_in[5];
    const float* Wo = (const float*)d_in[6];
    const int* seqp = (const int*)d_in[7];
    float* out = (float*)d_out;

    rope_table_kernel<<<64, 1024>>>();
    split_kernel<<<512, 256>>>(x);
    mma_gemm_kernel<<<dim3(32, QKV_KSPLIT, 3), 256>>>(Wq, Wk, Wv, QKV_KSPLIT);
    attn_kernel<<<dim3(NB * NH, NSPLIT), 256>>>(kc, vc, seqp);
    combine_kernel<<<NB * NH, 128>>>();
    mma_gemm_kernel<<<dim3(32, 16, 1), 256>>>(Wo, Wo, Wo, 16);
    reduce_kernel<<<128, 256>>>(out, 16);
}

// round 15
// speedup vs baseline: 2.6088x; 1.0657x over previous
#include <cuda_runtime.h>
#include <math.h>

#define NB 32
#define NH 32
#define DMODEL 4096
#define DKH 128
#define SINKC 4
#define WINDOWC 1020
#define MAXC (SINKC + WINDOWC)   /* 1024 */
#define KT 32                    /* gemm k-tile staged in smem */
#define QKV_KSPLIT 8
#define NSPLIT 4                 /* attention position partitions */
#define PART (MAXC / NSPLIT)     /* 256 positions per partition */
#define CHUNK 32                 /* attention rows per cp.async stage */
#define NCH (PART / CHUNK)       /* 8 chunks per partition */

// Scratch (device globals: no allocation allowed)
__device__ float  g_cos[MAXC * 64];
__device__ float  g_sin[MAXC * 64];
__device__ float2 g_xs[NB * DMODEL];                  // split activations (hi,lo)
__device__ float  g_part[24 * NB * DMODEL];           // GEMM K-split partials
__device__ float  g_split[NB * NH * NSPLIT * 132];    // per-partition m,S,acc

// ---------------------------------------------------------------------------
__device__ __forceinline__ unsigned tf32_rna(float x) {
    unsigned r;
    asm("cvt.rna.tf32.f32 %0, %1;" : "=r"(r) : "f"(x));
    return r;
}

__device__ __forceinline__ void mma_tf32(float& d0, float& d1, float& d2, float& d3,
                                         unsigned a0, unsigned a1, unsigned a2, unsigned a3,
                                         unsigned b0, unsigned b1) {
    asm("mma.sync.aligned.m16n8k8.row.col.f32.tf32.tf32.f32 "
        "{%0,%1,%2,%3}, {%4,%5,%6,%7}, {%8,%9}, {%0,%1,%2,%3};"
        : "+f"(d0), "+f"(d1), "+f"(d2), "+f"(d3)
        : "r"(a0), "r"(a1), "r"(a2), "r"(a3), "r"(b0), "r"(b1));
}

__device__ __forceinline__ void cp16(void* smem_dst, const void* gsrc) {
    unsigned d = (unsigned)__cvta_generic_to_shared(smem_dst);
    asm volatile("cp.async.cg.shared.global [%0], [%1], 16;" :: "r"(d), "l"(gsrc));
}
#define CP_COMMIT() asm volatile("cp.async.commit_group;")
#define CP_WAIT1()  asm volatile("cp.async.wait_group 1;")
#define CP_WAIT0()  asm volatile("cp.async.wait_group 0;")

// ---------------------------------------------------------------------------
// RoPE tables: cos/sin(pos * theta_j), theta_j = 10000^(-j/64), fp32 like ref
// ---------------------------------------------------------------------------
__global__ void rope_table_kernel() {
    int i = blockIdx.x * blockDim.x + threadIdx.x;   // 0 .. MAXC*64-1
    int pos = i >> 6;
    int j = i & 63;
    float theta = powf(10000.0f, -(float)j / 64.0f);
    float ang = (float)pos * theta;
    float s, c;
    sincosf(ang, &s, &c);
    g_cos[i] = c;
    g_sin[i] = s;
}

// ---------------------------------------------------------------------------
// Split activations into (hi, lo) tf32 pair for 3xTF32.
// ---------------------------------------------------------------------------
__global__ void split_kernel(const float* __restrict__ src) {
    int i = blockIdx.x * blockDim.x + threadIdx.x;   // 0 .. NB*DMODEL-1
    float v = src[i];
    unsigned hb = tf32_rna(v);
    float hf = __uint_as_float(hb);
    unsigned lb = tf32_rna(v - hf);
    g_xs[i] = make_float2(hf, __uint_as_float(lb));
}

// ---------------------------------------------------------------------------
// tf32 MMA GEMM, cp.async double-buffered (unchanged).
// ---------------------------------------------------------------------------
__global__ void mma_gemm_kernel(const float* __restrict__ Wa,
                                const float* __restrict__ Wb,
                                const float* __restrict__ Wc,
                                int ksplit) {
    __shared__ float  sw[2][128 * 36];
    __shared__ float2 sb[2][32 * 36];

    int slot = blockIdx.z;
    const float* W = (slot == 0) ? Wa : (slot == 1) ? Wb : Wc;
    int tid = threadIdx.x;
    int warp = tid >> 5;
    int lane = tid & 31;
    int r = lane >> 2;
    int c = lane & 3;
    int rowbase = blockIdx.x * 128;
    int kchunk = DMODEL / ksplit;
    int ntiles = kchunk / KT;
    int kb = blockIdx.y * kchunk;

    int wrow0 = tid >> 3;
    int wc4   = (tid & 7) << 2;
    int bb0   = tid >> 4;
    int bc4   = tid & 15;

    float d[4][4];
    #pragma unroll
    for (int t = 0; t < 4; t++)
        d[t][0] = d[t][1] = d[t][2] = d[t][3] = 0.0f;

    {
        int kt = kb;
        #pragma unroll
        for (int i = 0; i < 4; i++) {
            int row = wrow0 + i * 32;
            cp16(&sw[0][row * 36 + wc4],
                 W + (size_t)(rowbase + row) * DMODEL + kt + wc4);
        }
        #pragma unroll
        for (int i = 0; i < 2; i++) {
            int bbv = bb0 + i * 16;
            cp16(&sb[0][bbv * 36 + bc4 * 2],
                 (const float4*)g_xs + (size_t)bbv * (DMODEL / 2) + (kt >> 1) + bc4);
        }
        CP_COMMIT();
    }

    for (int t = 0; t < ntiles; t++) {
        int st = t & 1;
        if (t + 1 < ntiles) {
            int kt = kb + (t + 1) * KT;
            int ns = (t + 1) & 1;
            #pragma unroll
            for (int i = 0; i < 4; i++) {
                int row = wrow0 + i * 32;
                cp16(&sw[ns][row * 36 + wc4],
                     W + (size_t)(rowbase + row) * DMODEL + kt + wc4);
            }
            #pragma unroll
            for (int i = 0; i < 2; i++) {
                int bbv = bb0 + i * 16;
                cp16(&sb[ns][bbv * 36 + bc4 * 2],
                     (const float4*)g_xs + (size_t)bbv * (DMODEL / 2) + (kt >> 1) + bc4);
            }
            CP_COMMIT();
            CP_WAIT1();
        } else {
            CP_WAIT0();
        }
        __syncthreads();

        const float*  swp = sw[st];
        const float2* sbp = sb[st];
        #pragma unroll
        for (int ko = 0; ko < KT; ko += 8) {
            const float* wrow = swp + (warp * 16 + r) * 36 + ko + c;
            float wa0 = wrow[0];
            float wa1 = wrow[8 * 36];
            float wa2 = wrow[4];
            float wa3 = wrow[8 * 36 + 4];
            unsigned ah0 = __float_as_uint(wa0) & 0xffffe000u;
            unsigned ah1 = __float_as_uint(wa1) & 0xffffe000u;
            unsigned ah2 = __float_as_uint(wa2) & 0xffffe000u;
            unsigned ah3 = __float_as_uint(wa3) & 0xffffe000u;
            unsigned al0 = __float_as_uint(wa0 - __uint_as_float(ah0));
            unsigned al1 = __float_as_uint(wa1 - __uint_as_float(ah1));
            unsigned al2 = __float_as_uint(wa2 - __uint_as_float(ah2));
            unsigned al3 = __float_as_uint(wa3 - __uint_as_float(ah3));

            #pragma unroll
            for (int tb = 0; tb < 4; tb++) {
                float2 xb0 = sbp[(tb * 8 + r) * 36 + ko + c];
                float2 xb1 = sbp[(tb * 8 + r) * 36 + ko + c + 4];
                unsigned bh0 = __float_as_uint(xb0.x), bh1 = __float_as_uint(xb1.x);
                unsigned bl0 = __float_as_uint(xb0.y), bl1 = __float_as_uint(xb1.y);
                mma_tf32(d[tb][0], d[tb][1], d[tb][2], d[tb][3], ah0, ah1, ah2, ah3, bl0, bl1);
                mma_tf32(d[tb][0], d[tb][1], d[tb][2], d[tb][3], al0, al1, al2, al3, bh0, bh1);
                mma_tf32(d[tb][0], d[tb][1], d[tb][2], d[tb][3], ah0, ah1, ah2, ah3, bh0, bh1);
            }
        }
        __syncthreads();
    }

    int n0 = rowbase + warp * 16;
    float* pp = g_part + (size_t)(slot * ksplit + blockIdx.y) * NB * DMODEL;
    #pragma unroll
    for (int t = 0; t < 4; t++) {
        int bt = t * 8;
        pp[(size_t)(bt + 2 * c)     * DMODEL + n0 + r]     = d[t][0];
        pp[(size_t)(bt + 2 * c + 1) * DMODEL + n0 + r]     = d[t][1];
        pp[(size_t)(bt + 2 * c)     * DMODEL + n0 + r + 8] = d[t][2];
        pp[(size_t)(bt + 2 * c + 1) * DMODEL + n0 + r + 8] = d[t][3];
    }
}

// ---------------------------------------------------------------------------
// Reduce ksplit partials (W_O only). Layout [ks][b][n], slot 0.
// ---------------------------------------------------------------------------
__global__ void reduce_kernel(float* __restrict__ dst, int ksplit) {
    int i = blockIdx.x * blockDim.x + threadIdx.x;
    int per_slot = NB * (DMODEL / 4);
    if (i >= per_slot) return;
    const float4* src = (const float4*)g_part + i;
    float4 s = make_float4(0.f, 0.f, 0.f, 0.f);
    for (int k = 0; k < ksplit; k++) {
        float4 v = src[(size_t)k * per_slot];
        s.x += v.x; s.y += v.y; s.z += v.z; s.w += v.w;
    }
    ((float4*)dst)[i] = s;
}

// ---------------------------------------------------------------------------
// Attention, flash-decode split + cp.async K/V staging.
// grid (NB*NH, NSPLIT), 256 threads. Each block handles PART positions of one
// (b,h): K rows stream through a 2-stage cp.async smem pipeline (CHUNK rows =
// 16 KB per stage), scores computed from LDS; same for V. Position L-1's row
// is patched into the staged chunk from the freshly reduced k_new/v_new.
// Emits unnormalized (m, S, acc[128]) to g_split. Caches NOT mutated.
// ---------------------------------------------------------------------------
__device__ __forceinline__ int cache_row(int p, bool full, int ins, int part2) {
    if (!full || p < SINKC) return p;
    return (p < SINKC + part2) ? (ins + 1 + (p - SINKC))
                               : (SINKC + (p - SINKC - part2));
}

__global__ void attn_kernel(const float* __restrict__ kcache,
                            const float* __restrict__ vcache,
                            const int* __restrict__ seqp) {
    __shared__ float stage[2][CHUNK * DKH];            // 32 KB
    __shared__ __align__(16) float q_raw[DKH];
    __shared__ __align__(16) float knew_s[DKH];
    __shared__ __align__(16) float vnew_s[DKH];
    __shared__ float q_rot[DKH];
    __shared__ float scores[PART];
    __shared__ float outp[8][DKH];
    __shared__ float red[8];

    int bh = blockIdx.x;
    int sp = blockIdx.y;
    int b = bh >> 5;
    int h = bh & 31;
    int tid = threadIdx.x, warp = tid >> 5, lane = tid & 31;

    int seq = *seqp;
    int L, ins, part2;
    bool full;
    if (seq < MAXC) { L = seq + 1; ins = seq; part2 = 0; full = false; }
    else { L = MAXC; ins = SINKC + (seq - SINKC) % WINDOWC; part2 = MAXC - (ins + 1); full = true; }

    int ps = sp * PART;
    int pe = min(ps + PART, L);
    bool need_new = (L - 1 >= ps) && (L - 1 < ps + PART);

    const float* kbf = kcache + (size_t)bh * MAXC * DKH;
    const float* vbf = vcache + (size_t)bh * MAXC * DKH;

    // Per-thread staging coords: row = tid>>3 (32 rows), 4x16B per thread.
    int srow = tid >> 3;
    int scol = (tid & 7) << 2;

    // Issue one chunk of 32 rows into stage st. Rows >= L clamp to row 0.
    auto issue_chunk = [&](const float* base, int ch, int st) {
        int p = ps + ch * CHUNK + srow;
        int cr = (p < L) ? cache_row(p, full, ins, part2) : 0;
        const float* src = base + (size_t)cr * DKH + scol;
        float* dst = &stage[st][srow * DKH + scol];
        #pragma unroll
        for (int j = 0; j < 4; j++)
            cp16(dst + j * 32, src + j * 32);
        CP_COMMIT();
    };

    // Patch row L-1 with fresh k_new/v_new (chunk-uniform condition).
    auto fix_row = [&](int ch, int st, const float* newv) {
        int fr = (L - 1) - (ps + ch * CHUNK);
        if (fr >= 0 && fr < CHUNK) {
            if (tid < DKH) stage[st][fr * DKH + tid] = newv[tid];
            __syncthreads();
        }
    };

    // ---- prologue: reduce QKV K-split partials for this (b,h) ----
    for (int i = tid; i < 3 * DKH; i += 256) {
        int slot = i >> 7;           // 0=q, 1=k_new, 2=v_new
        if (slot != 0 && !need_new) continue;
        int d = i & (DKH - 1);
        const float* base = g_part
            + ((size_t)(slot * QKV_KSPLIT) * NB + b) * DMODEL + h * DKH + d;
        float s = 0.0f;
        #pragma unroll
        for (int ks = 0; ks < QKV_KSPLIT; ks++)
            s += base[(size_t)ks * NB * DMODEL];
        if (slot == 0) q_raw[d] = s;
        else if (slot == 1) knew_s[d] = s;
        else vnew_s[d] = s;
    }

    // Start K pipeline while prologue finishes elsewhere
    issue_chunk(kbf, 0, 0);
    __syncthreads();

    if (tid < DKH) {
        float qv = q_raw[tid];
        float pn = q_raw[tid ^ 64];
        int j = tid & 63;
        float c = g_cos[(L - 1) * 64 + j];
        float s = g_sin[(L - 1) * 64 + j];
        float flip = (tid < 64) ? -pn : pn;
        q_rot[tid] = qv * c + flip * s;
    }
    __syncthreads();

    float4 qf = *(const float4*)(q_rot + lane * 4);
    int j4 = (lane & 15) << 2;
    float sgn = (lane < 16) ? -1.0f : 1.0f;

    // ---- phase 1: scores, K chunks through the pipeline ----
    for (int ch = 0; ch < NCH; ch++) {
        int st = ch & 1;
        if (ch + 1 < NCH) { issue_chunk(kbf, ch + 1, st ^ 1); CP_WAIT1(); }
        else              { CP_WAIT0(); }
        __syncthreads();
        fix_row(ch, st, knew_s);

        const float* stp = stage[st];
        int pb = ps + ch * CHUNK;
        #pragma unroll
        for (int half = 0; half < 2; half++) {
            int rA = warp + half * 16;
            int rB = rA + 8;
            int pA = pb + rA, pB = pb + rB;
            // Issue table loads first (L2), then LDS
            float4 csA = *(const float4*)(g_cos + pA * 64 + j4);
            float4 snA = *(const float4*)(g_sin + pA * 64 + j4);
            float4 csB = *(const float4*)(g_cos + pB * 64 + j4);
            float4 snB = *(const float4*)(g_sin + pB * 64 + j4);
            float4 kvA = *(const float4*)(stp + rA * DKH + lane * 4);
            float4 kvB = *(const float4*)(stp + rB * DKH + lane * 4);

            float4 pvA, pvB;
            pvA.x = __shfl_xor_sync(0xffffffffu, kvA.x, 16);
            pvB.x = __shfl_xor_sync(0xffffffffu, kvB.x, 16);
            pvA.y = __shfl_xor_sync(0xffffffffu, kvA.y, 16);
            pvB.y = __shfl_xor_sync(0xffffffffu, kvB.y, 16);
            pvA.z = __shfl_xor_sync(0xffffffffu, kvA.z, 16);
            pvB.z = __shfl_xor_sync(0xffffffffu, kvB.z, 16);
            pvA.w = __shfl_xor_sync(0xffffffffu, kvA.w, 16);
            pvB.w = __shfl_xor_sync(0xffffffffu, kvB.w, 16);

            float dA = (kvA.x * csA.x + sgn * pvA.x * snA.x) * qf.x
                     + (kvA.y * csA.y + sgn * pvA.y * snA.y) * qf.y
                     + (kvA.z * csA.z + sgn * pvA.z * snA.z) * qf.z
                     + (kvA.w * csA.w + sgn * pvA.w * snA.w) * qf.w;
            float dB = (kvB.x * csB.x + sgn * pvB.x * snB.x) * qf.x
                     + (kvB.y * csB.y + sgn * pvB.y * snB.y) * qf.y
                     + (kvB.z * csB.z + sgn * pvB.z * snB.z) * qf.z
                     + (kvB.w * csB.w + sgn * pvB.w * snB.w) * qf.w;
            #pragma unroll
            for (int o = 16; o > 0; o >>= 1) {
                dA += __shfl_xor_sync(0xffffffffu, dA, o);
                dB += __shfl_xor_sync(0xffffffffu, dB, o);
            }
            if (lane == 0) {
                if (pA < pe) scores[pA - ps] = dA * 0.08838834764831845f;
                if (pB < pe) scores[pB - ps] = dB * 0.08838834764831845f;
            }
        }
        __syncthreads();
    }

    // Prefetch V chunk 0 (stage 0 free: last K compute used stage 1)
    issue_chunk(vbf, 0, 0);

    // ---- partition softmax stats ----
    int n = pe - ps;
    float m = -1e30f;
    for (int p = tid; p < n; p += 256) m = fmaxf(m, scores[p]);
    #pragma unroll
    for (int o = 16; o > 0; o >>= 1) m = fmaxf(m, __shfl_xor_sync(0xffffffffu, m, o));
    if (lane == 0) red[warp] = m;
    __syncthreads();
    m = red[0];
    #pragma unroll
    for (int w = 1; w < 8; w++) m = fmaxf(m, red[w]);

    float lsum = 0.0f;
    for (int p = tid; p < n; p += 256) {
        float e = __expf(scores[p] - m);
        scores[p] = e;
        lsum += e;
    }
    #pragma unroll
    for (int o = 16; o > 0; o >>= 1) lsum += __shfl_xor_sync(0xffffffffu, lsum, o);
    __syncthreads();
    if (lane == 0) red[warp] = lsum;
    __syncthreads();
    float S = 0.0f;
    #pragma unroll
    for (int w = 0; w < 8; w++) S += red[w];

    // ---- phase 2: unnormalized acc, V chunks through the pipeline ----
    float4 acc = make_float4(0.f, 0.f, 0.f, 0.f);
    for (int ch = 0; ch < NCH; ch++) {
        int st = ch & 1;
        if (ch + 1 < NCH) { issue_chunk(vbf, ch + 1, st ^ 1); CP_WAIT1(); }
        else              { CP_WAIT0(); }
        __syncthreads();
        fix_row(ch, st, vnew_s);

        const float* stp = stage[st];
        int pb = ps + ch * CHUNK;
        #pragma unroll
        for (int half = 0; half < 2; half++) {
            int rA = warp + half * 16;
            int rB = rA + 8;
            int pA = pb + rA, pB = pb + rB;
            float wA = (pA < pe) ? scores[pA - ps] : 0.0f;
            float wB = (pB < pe) ? scores[pB - ps] : 0.0f;
            float4 vvA = *(const float4*)(stp + rA * DKH + lane * 4);
            float4 vvB = *(const float4*)(stp + rB * DKH + lane * 4);
            acc.x += wA * vvA.x + wB * vvB.x;
            acc.y += wA * vvA.y + wB * vvB.y;
            acc.z += wA * vvA.z + wB * vvB.z;
            acc.w += wA * vvA.w + wB * vvB.w;
        }
        __syncthreads();
    }

    *(float4*)(&outp[warp][lane * 4]) = acc;
    __syncthreads();

    float* dst = g_split + ((size_t)bh * NSPLIT + sp) * 132;
    if (tid < DKH) {
        float s = 0.0f;
        #pragma unroll
        for (int w = 0; w < 8; w++) s += outp[w][tid];
        dst[tid] = s;
    } else if (tid == 128) {
        dst[128] = m;
        dst[129] = S;
    }
}

// ---------------------------------------------------------------------------
// Combine partitions: out = (sum_s w_s acc_s) / (sum_s w_s S_s), w_s=e^{m_s-m}.
// Writes the tf32 hi/lo split activations for the W_O GEMM.
// ---------------------------------------------------------------------------
__global__ void combine_kernel() {
    __shared__ float w[NSPLIT];
    __shared__ float Ssh;
    int bh = blockIdx.x;
    int tid = threadIdx.x;
    int b = bh >> 5;
    int h = bh & 31;
    const float* base = g_split + (size_t)bh * NSPLIT * 132;

    if (tid == 0) {
        float ms[NSPLIT], Ss[NSPLIT];
        float m = -1e30f;
        #pragma unroll
        for (int s = 0; s < NSPLIT; s++) {
            ms[s] = base[s * 132 + 128];
            Ss[s] = base[s * 132 + 129];
            m = fmaxf(m, ms[s]);
        }
        float S = 0.0f;
        #pragma unroll
        for (int s = 0; s < NSPLIT; s++) {
            float ws = __expf(ms[s] - m);
            w[s] = ws;
            S += ws * Ss[s];
        }
        Ssh = S;
    }
    __syncthreads();

    float a = 0.0f;
    #pragma unroll
    for (int s = 0; s < NSPLIT; s++) a += w[s] * base[s * 132 + tid];
    float v = a / Ssh;
    unsigned hb = tf32_rna(v);
    float hf = __uint_as_float(hb);
    unsigned lb = tf32_rna(v - hf);
    g_xs[(size_t)b * DMODEL + h * DKH + tid] = make_float2(hf, __uint_as_float(lb));
}

// ---------------------------------------------------------------------------
extern "C" void kernel_launch(void* const* d_in, const int* in_sizes, int n_in,
                              void* d_out, int out_size) {
    const float* x  = (const float*)d_in[0];
    const float* kc = (const float*)d_in[1];
    const float* vc = (const float*)d_in[2];
    const float* Wq = (const float*)d_in[3];
    const float* Wk = (const float*)d_in[4];
    const float* Wv = (const float*)d_in[5];
    const float* Wo = (const float*)d_in[6];
    const int* seqp = (const int*)d_in[7];
    float* out = (float*)d_out;

    rope_table_kernel<<<64, 1024>>>();
    split_kernel<<<512, 256>>>(x);
    mma_gemm_kernel<<<dim3(32, QKV_KSPLIT, 3), 256>>>(Wq, Wk, Wv, QKV_KSPLIT);
    attn_kernel<<<dim3(NB * NH, NSPLIT), 256>>>(kc, vc, seqp);
    combine_kernel<<<NB * NH, 128>>>();
    mma_gemm_kernel<<<dim3(32, 16, 1), 256>>>(Wo, Wo, Wo, 16);
    reduce_kernel<<<128, 256>>>(out, 16);
}

// round 16
// speedup vs baseline: 3.2298x; 1.2381x over previous
#include <cuda_runtime.h>
#include <math.h>

#define NB 32
#define NH 32
#define DMODEL 4096
#define DKH 128
#define SINKC 4
#define WINDOWC 1020
#define MAXC (SINKC + WINDOWC)   /* 1024 */
#define KT 32                    /* gemm k-tile staged in smem */
#define QKV_KSPLIT 8
#define NSPLIT 4                 /* attention position partitions */
#define PART (MAXC / NSPLIT)     /* 256 positions per partition */
#define CHUNK 32                 /* attention rows per cp.async stage */
#define NCHMAX (PART / CHUNK)    /* 8 chunks per partition */

// Attention dynamic smem layout (floats):
//   stage[2] @ 0, 8192 each: K/V rows at +0 (32*128), cos at +4096, sin at +6144
//   q_raw 16384, knew 16512, vnew 16640, q_rot 16768,
//   scores 16896 (256), outp 17152 (8*128), red 18176 (8)
#define ATTN_SMEM_FLOATS 18184
#define A_STAGE(st) ((st) * 8192)
#define A_COS 4096
#define A_SIN 6144
#define A_QRAW 16384
#define A_KNEW 16512
#define A_VNEW 16640
#define A_QROT 16768
#define A_SCORES 16896
#define A_OUTP 17152
#define A_RED 18176

// Scratch (device globals: no allocation allowed)
__device__ float  g_cos[MAXC * 64];
__device__ float  g_sin[MAXC * 64];
__device__ float2 g_xs[NB * DMODEL];                  // split activations (hi,lo)
__device__ float  g_part[24 * NB * DMODEL];           // GEMM K-split partials
__device__ float  g_split[NB * NH * NSPLIT * 132];    // per-partition m,S,acc

// ---------------------------------------------------------------------------
__device__ __forceinline__ unsigned tf32_rna(float x) {
    unsigned r;
    asm("cvt.rna.tf32.f32 %0, %1;" : "=r"(r) : "f"(x));
    return r;
}

__device__ __forceinline__ void mma_tf32(float& d0, float& d1, float& d2, float& d3,
                                         unsigned a0, unsigned a1, unsigned a2, unsigned a3,
                                         unsigned b0, unsigned b1) {
    asm("mma.sync.aligned.m16n8k8.row.col.f32.tf32.tf32.f32 "
        "{%0,%1,%2,%3}, {%4,%5,%6,%7}, {%8,%9}, {%0,%1,%2,%3};"
        : "+f"(d0), "+f"(d1), "+f"(d2), "+f"(d3)
        : "r"(a0), "r"(a1), "r"(a2), "r"(a3), "r"(b0), "r"(b1));
}

__device__ __forceinline__ void cp16(void* smem_dst, const void* gsrc) {
    unsigned d = (unsigned)__cvta_generic_to_shared(smem_dst);
    asm volatile("cp.async.cg.shared.global [%0], [%1], 16;" :: "r"(d), "l"(gsrc));
}
#define CP_COMMIT() asm volatile("cp.async.commit_group;")
#define CP_WAIT1()  asm volatile("cp.async.wait_group 1;")
#define CP_WAIT0()  asm volatile("cp.async.wait_group 0;")

// ---------------------------------------------------------------------------
// RoPE tables: cos/sin(pos * theta_j), theta_j = 10000^(-j/64), fp32 like ref
// ---------------------------------------------------------------------------
__global__ void rope_table_kernel() {
    int i = blockIdx.x * blockDim.x + threadIdx.x;   // 0 .. MAXC*64-1
    int pos = i >> 6;
    int j = i & 63;
    float theta = powf(10000.0f, -(float)j / 64.0f);
    float ang = (float)pos * theta;
    float s, c;
    sincosf(ang, &s, &c);
    g_cos[i] = c;
    g_sin[i] = s;
}

// ---------------------------------------------------------------------------
// Split activations into (hi, lo) tf32 pair for 3xTF32.
// ---------------------------------------------------------------------------
__global__ void split_kernel(const float* __restrict__ src) {
    int i = blockIdx.x * blockDim.x + threadIdx.x;   // 0 .. NB*DMODEL-1
    float v = src[i];
    unsigned hb = tf32_rna(v);
    float hf = __uint_as_float(hb);
    unsigned lb = tf32_rna(v - hf);
    g_xs[i] = make_float2(hf, __uint_as_float(lb));
}

// ---------------------------------------------------------------------------
// tf32 MMA GEMM, cp.async double-buffered (unchanged).
// ---------------------------------------------------------------------------
__global__ void mma_gemm_kernel(const float* __restrict__ Wa,
                                const float* __restrict__ Wb,
                                const float* __restrict__ Wc,
                                int ksplit) {
    __shared__ float  sw[2][128 * 36];
    __shared__ float2 sb[2][32 * 36];

    int slot = blockIdx.z;
    const float* W = (slot == 0) ? Wa : (slot == 1) ? Wb : Wc;
    int tid = threadIdx.x;
    int warp = tid >> 5;
    int lane = tid & 31;
    int r = lane >> 2;
    int c = lane & 3;
    int rowbase = blockIdx.x * 128;
    int kchunk = DMODEL / ksplit;
    int ntiles = kchunk / KT;
    int kb = blockIdx.y * kchunk;

    int wrow0 = tid >> 3;
    int wc4   = (tid & 7) << 2;
    int bb0   = tid >> 4;
    int bc4   = tid & 15;

    float d[4][4];
    #pragma unroll
    for (int t = 0; t < 4; t++)
        d[t][0] = d[t][1] = d[t][2] = d[t][3] = 0.0f;

    {
        int kt = kb;
        #pragma unroll
        for (int i = 0; i < 4; i++) {
            int row = wrow0 + i * 32;
            cp16(&sw[0][row * 36 + wc4],
                 W + (size_t)(rowbase + row) * DMODEL + kt + wc4);
        }
        #pragma unroll
        for (int i = 0; i < 2; i++) {
            int bbv = bb0 + i * 16;
            cp16(&sb[0][bbv * 36 + bc4 * 2],
                 (const float4*)g_xs + (size_t)bbv * (DMODEL / 2) + (kt >> 1) + bc4);
        }
        CP_COMMIT();
    }

    for (int t = 0; t < ntiles; t++) {
        int st = t & 1;
        if (t + 1 < ntiles) {
            int kt = kb + (t + 1) * KT;
            int ns = (t + 1) & 1;
            #pragma unroll
            for (int i = 0; i < 4; i++) {
                int row = wrow0 + i * 32;
                cp16(&sw[ns][row * 36 + wc4],
                     W + (size_t)(rowbase + row) * DMODEL + kt + wc4);
            }
            #pragma unroll
            for (int i = 0; i < 2; i++) {
                int bbv = bb0 + i * 16;
                cp16(&sb[ns][bbv * 36 + bc4 * 2],
                     (const float4*)g_xs + (size_t)bbv * (DMODEL / 2) + (kt >> 1) + bc4);
            }
            CP_COMMIT();
            CP_WAIT1();
        } else {
            CP_WAIT0();
        }
        __syncthreads();

        const float*  swp = sw[st];
        const float2* sbp = sb[st];
        #pragma unroll
        for (int ko = 0; ko < KT; ko += 8) {
            const float* wrow = swp + (warp * 16 + r) * 36 + ko + c;
            float wa0 = wrow[0];
            float wa1 = wrow[8 * 36];
            float wa2 = wrow[4];
            float wa3 = wrow[8 * 36 + 4];
            unsigned ah0 = __float_as_uint(wa0) & 0xffffe000u;
            unsigned ah1 = __float_as_uint(wa1) & 0xffffe000u;
            unsigned ah2 = __float_as_uint(wa2) & 0xffffe000u;
            unsigned ah3 = __float_as_uint(wa3) & 0xffffe000u;
            unsigned al0 = __float_as_uint(wa0 - __uint_as_float(ah0));
            unsigned al1 = __float_as_uint(wa1 - __uint_as_float(ah1));
            unsigned al2 = __float_as_uint(wa2 - __uint_as_float(ah2));
            unsigned al3 = __float_as_uint(wa3 - __uint_as_float(ah3));

            #pragma unroll
            for (int tb = 0; tb < 4; tb++) {
                float2 xb0 = sbp[(tb * 8 + r) * 36 + ko + c];
                float2 xb1 = sbp[(tb * 8 + r) * 36 + ko + c + 4];
                unsigned bh0 = __float_as_uint(xb0.x), bh1 = __float_as_uint(xb1.x);
                unsigned bl0 = __float_as_uint(xb0.y), bl1 = __float_as_uint(xb1.y);
                mma_tf32(d[tb][0], d[tb][1], d[tb][2], d[tb][3], ah0, ah1, ah2, ah3, bl0, bl1);
                mma_tf32(d[tb][0], d[tb][1], d[tb][2], d[tb][3], al0, al1, al2, al3, bh0, bh1);
                mma_tf32(d[tb][0], d[tb][1], d[tb][2], d[tb][3], ah0, ah1, ah2, ah3, bh0, bh1);
            }
        }
        __syncthreads();
    }

    int n0 = rowbase + warp * 16;
    float* pp = g_part + (size_t)(slot * ksplit + blockIdx.y) * NB * DMODEL;
    #pragma unroll
    for (int t = 0; t < 4; t++) {
        int bt = t * 8;
        pp[(size_t)(bt + 2 * c)     * DMODEL + n0 + r]     = d[t][0];
        pp[(size_t)(bt + 2 * c + 1) * DMODEL + n0 + r]     = d[t][1];
        pp[(size_t)(bt + 2 * c)     * DMODEL + n0 + r + 8] = d[t][2];
        pp[(size_t)(bt + 2 * c + 1) * DMODEL + n0 + r + 8] = d[t][3];
    }
}

// ---------------------------------------------------------------------------
// Reduce ksplit partials (W_O only). Layout [ks][b][n], slot 0.
// ---------------------------------------------------------------------------
__global__ void reduce_kernel(float* __restrict__ dst, int ksplit) {
    int i = blockIdx.x * blockDim.x + threadIdx.x;
    int per_slot = NB * (DMODEL / 4);
    if (i >= per_slot) return;
    const float4* src = (const float4*)g_part + i;
    float4 s = make_float4(0.f, 0.f, 0.f, 0.f);
    for (int k = 0; k < ksplit; k++) {
        float4 v = src[(size_t)k * per_slot];
        s.x += v.x; s.y += v.y; s.z += v.z; s.w += v.w;
    }
    ((float4*)dst)[i] = s;
}

// ---------------------------------------------------------------------------
// Attention: flash-decode split + cp.async staging of K/V AND cos/sin tables.
// grid (NB*NH, NSPLIT), 256 threads, ~71 KB dynamic smem (3 blocks/SM).
// Phase 1 inner loop is pure LDS: half-warp per position, RoPE pair (d,d+64)
// held within a lane (no flip shuffles), 4-step butterfly reduce.
// Caches NOT mutated; row L-1 patched with freshly reduced k_new/v_new.
// ---------------------------------------------------------------------------
__device__ __forceinline__ int cache_row(int p, bool full, int ins, int part2) {
    if (!full || p < SINKC) return p;
    return (p < SINKC + part2) ? (ins + 1 + (p - SINKC))
                               : (SINKC + (p - SINKC - part2));
}

__global__ void attn_kernel(const float* __restrict__ kcache,
                            const float* __restrict__ vcache,
                            const int* __restrict__ seqp) {
    extern __shared__ float sm[];
    float* scores = sm + A_SCORES;
    float* red    = sm + A_RED;

    int bh = blockIdx.x;
    int sp = blockIdx.y;
    int b = bh >> 5;
    int h = bh & 31;
    int tid = threadIdx.x, warp = tid >> 5, lane = tid & 31;
    int l16 = lane & 15, hw = lane >> 4;

    int seq = *seqp;
    int L, ins, part2;
    bool full;
    if (seq < MAXC) { L = seq + 1; ins = seq; part2 = 0; full = false; }
    else { L = MAXC; ins = SINKC + (seq - SINKC) % WINDOWC; part2 = MAXC - (ins + 1); full = true; }

    int ps = sp * PART;
    int pe = min(ps + PART, L);
    int nch = 0;
    if (pe > ps) nch = min(NCHMAX, (pe - ps + CHUNK - 1) / CHUNK);
    bool need_new = (L - 1 >= ps) && (L - 1 < ps + PART);

    const float* kbf = kcache + (size_t)bh * MAXC * DKH;
    const float* vbf = vcache + (size_t)bh * MAXC * DKH;

    int srow = tid >> 3;
    int scol = (tid & 7) << 2;

    // K chunk + table staging (one commit group)
    auto issue_k = [&](int ch, int st) {
        int p = ps + ch * CHUNK + srow;
        int cr = (p < L) ? cache_row(p, full, ins, part2) : 0;
        const float* src = kbf + (size_t)cr * DKH + scol;
        float* dst = sm + A_STAGE(st) + srow * DKH + scol;
        #pragma unroll
        for (int j = 0; j < 4; j++) cp16(dst + j * 32, src + j * 32);
        int tb = (ps + ch * CHUNK) * 64;
        float* cdst = sm + A_STAGE(st) + A_COS + tid * 8;
        const float* csrc = g_cos + tb + tid * 8;
        cp16(cdst, csrc); cp16(cdst + 4, csrc + 4);
        float* sdst = sm + A_STAGE(st) + A_SIN + tid * 8;
        const float* ssrc = g_sin + tb + tid * 8;
        cp16(sdst, ssrc); cp16(sdst + 4, ssrc + 4);
        CP_COMMIT();
    };
    // V chunk staging (no tables)
    auto issue_v = [&](int ch, int st) {
        int p = ps + ch * CHUNK + srow;
        int cr = (p < L) ? cache_row(p, full, ins, part2) : 0;
        const float* src = vbf + (size_t)cr * DKH + scol;
        float* dst = sm + A_STAGE(st) + srow * DKH + scol;
        #pragma unroll
        for (int j = 0; j < 4; j++) cp16(dst + j * 32, src + j * 32);
        CP_COMMIT();
    };
    // Patch row L-1 with fresh k_new/v_new (chunk-uniform condition).
    auto fix_row = [&](int ch, int st, const float* newv) {
        int fr = (L - 1) - (ps + ch * CHUNK);
        if (fr >= 0 && fr < CHUNK) {
            if (tid < DKH) sm[A_STAGE(st) + fr * DKH + tid] = newv[tid];
            __syncthreads();
        }
    };

    // ---- prologue: reduce QKV K-split partials for this (b,h) ----
    for (int i = tid; i < 3 * DKH; i += 256) {
        int slot = i >> 7;           // 0=q, 1=k_new, 2=v_new
        if (slot != 0 && !need_new) continue;
        int d = i & (DKH - 1);
        const float* base = g_part
            + ((size_t)(slot * QKV_KSPLIT) * NB + b) * DMODEL + h * DKH + d;
        float s = 0.0f;
        #pragma unroll
        for (int ks = 0; ks < QKV_KSPLIT; ks++)
            s += base[(size_t)ks * NB * DMODEL];
        float* dsts = (slot == 0) ? (sm + A_QRAW) : (slot == 1) ? (sm + A_KNEW) : (sm + A_VNEW);
        dsts[d] = s;
    }
    if (nch > 0) issue_k(0, 0);
    __syncthreads();

    if (tid < DKH) {
        float qv = sm[A_QRAW + tid];
        float pn = sm[A_QRAW + (tid ^ 64)];
        int j = tid & 63;
        float c = g_cos[(L - 1) * 64 + j];
        float s = g_sin[(L - 1) * 64 + j];
        float flip = (tid < 64) ? -pn : pn;
        sm[A_QROT + tid] = qv * c + flip * s;
    }
    __syncthreads();

    // Per-lane q_rot slices: dims [4*l16, 4*l16+4) and +64.
    float4 ql = *(const float4*)(sm + A_QROT + l16 * 4);
    float4 qh = *(const float4*)(sm + A_QROT + 64 + l16 * 4);

    // ---- phase 1: scores (all-LDS inner loop) ----
    for (int ch = 0; ch < nch; ch++) {
        int st = ch & 1;
        if (ch + 1 < nch) { issue_k(ch + 1, st ^ 1); CP_WAIT1(); }
        else              { CP_WAIT0(); }
        __syncthreads();
        fix_row(ch, st, sm + A_KNEW);

        const float* stp = sm + A_STAGE(st);
        int pb = ps + ch * CHUNK;
        #pragma unroll
        for (int i = 0; i < 2; i++) {
            int row = warp * 4 + i * 2 + hw;   // half-warp owns one row
            int p = pb + row;
            const float* kr = stp + row * DKH;
            float4 klo = *(const float4*)(kr + l16 * 4);
            float4 khi = *(const float4*)(kr + 64 + l16 * 4);
            float4 c4 = *(const float4*)(stp + A_COS + row * 64 + l16 * 4);
            float4 s4 = *(const float4*)(stp + A_SIN + row * 64 + l16 * 4);

            float d = klo.x * (c4.x * ql.x + s4.x * qh.x)
                    + khi.x * (c4.x * qh.x - s4.x * ql.x)
                    + klo.y * (c4.y * ql.y + s4.y * qh.y)
                    + khi.y * (c4.y * qh.y - s4.y * ql.y)
                    + klo.z * (c4.z * ql.z + s4.z * qh.z)
                    + khi.z * (c4.z * qh.z - s4.z * ql.z)
                    + klo.w * (c4.w * ql.w + s4.w * qh.w)
                    + khi.w * (c4.w * qh.w - s4.w * ql.w);
            #pragma unroll
            for (int o = 8; o > 0; o >>= 1)
                d += __shfl_xor_sync(0xffffffffu, d, o);
            if (l16 == 0 && p < pe)
                scores[p - ps] = d * 0.08838834764831845f;   // 1/sqrt(128)
        }
        __syncthreads();
    }

    // Prefetch V chunk 0 into stage 0
    if (nch > 0) issue_v(0, 0);

    // ---- partition softmax stats ----
    int n = pe - ps;
    float m = -1e30f;
    for (int p = tid; p < n; p += 256) m = fmaxf(m, scores[p]);
    #pragma unroll
    for (int o = 16; o > 0; o >>= 1) m = fmaxf(m, __shfl_xor_sync(0xffffffffu, m, o));
    if (lane == 0) red[warp] = m;
    __syncthreads();
    m = red[0];
    #pragma unroll
    for (int w = 1; w < 8; w++) m = fmaxf(m, red[w]);

    float lsum = 0.0f;
    for (int p = tid; p < n; p += 256) {
        float e = __expf(scores[p] - m);
        scores[p] = e;
        lsum += e;
    }
    #pragma unroll
    for (int o = 16; o > 0; o >>= 1) lsum += __shfl_xor_sync(0xffffffffu, lsum, o);
    __syncthreads();
    if (lane == 0) red[warp] = lsum;
    __syncthreads();
    float S = 0.0f;
    #pragma unroll
    for (int w = 0; w < 8; w++) S += red[w];

    // ---- phase 2: unnormalized acc over V chunks ----
    float4 acc = make_float4(0.f, 0.f, 0.f, 0.f);
    for (int ch = 0; ch < nch; ch++) {
        int st = ch & 1;
        if (ch + 1 < nch) { issue_v(ch + 1, st ^ 1); CP_WAIT1(); }
        else              { CP_WAIT0(); }
        __syncthreads();
        fix_row(ch, st, sm + A_VNEW);

        const float* stp = sm + A_STAGE(st);
        int pb = ps + ch * CHUNK;
        #pragma unroll
        for (int i = 0; i < 4; i++) {
            int row = warp * 4 + i;
            int p = pb + row;
            float w8 = (p < pe) ? scores[p - ps] : 0.0f;
            float4 vv = *(const float4*)(stp + row * DKH + lane * 4);
            acc.x += w8 * vv.x;
            acc.y += w8 * vv.y;
            acc.z += w8 * vv.z;
            acc.w += w8 * vv.w;
        }
        __syncthreads();
    }

    *(float4*)(sm + A_OUTP + warp * DKH + lane * 4) = acc;
    __syncthreads();

    float* dst = g_split + ((size_t)bh * NSPLIT + sp) * 132;
    if (tid < DKH) {
        float s = 0.0f;
        #pragma unroll
        for (int w = 0; w < 8; w++) s += sm[A_OUTP + w * DKH + tid];
        dst[tid] = s;
    } else if (tid == 128) {
        dst[128] = m;
        dst[129] = S;
    }
}

// ---------------------------------------------------------------------------
// Combine partitions: out = (sum_s w_s acc_s) / (sum_s w_s S_s), w_s=e^{m_s-m}.
// Writes the tf32 hi/lo split activations for the W_O GEMM.
// ---------------------------------------------------------------------------
__global__ void combine_kernel() {
    __shared__ float w[NSPLIT];
    __shared__ float Ssh;
    int bh = blockIdx.x;
    int tid = threadIdx.x;
    int b = bh >> 5;
    int h = bh & 31;
    const float* base = g_split + (size_t)bh * NSPLIT * 132;

    if (tid == 0) {
        float ms[NSPLIT], Ss[NSPLIT];
        float m = -1e30f;
        #pragma unroll
        for (int s = 0; s < NSPLIT; s++) {
            ms[s] = base[s * 132 + 128];
            Ss[s] = base[s * 132 + 129];
            m = fmaxf(m, ms[s]);
        }
        float S = 0.0f;
        #pragma unroll
        for (int s = 0; s < NSPLIT; s++) {
            float ws = __expf(ms[s] - m);
            w[s] = ws;
            S += ws * Ss[s];
        }
        Ssh = S;
    }
    __syncthreads();

    float a = 0.0f;
    #pragma unroll
    for (int s = 0; s < NSPLIT; s++) a += w[s] * base[s * 132 + tid];
    float v = a / Ssh;
    unsigned hb = tf32_rna(v);
    float hf = __uint_as_float(hb);
    unsigned lb = tf32_rna(v - hf);
    g_xs[(size_t)b * DMODEL + h * DKH + tid] = make_float2(hf, __uint_as_float(lb));
}

// ---------------------------------------------------------------------------
extern "C" void kernel_launch(void* const* d_in, const int* in_sizes, int n_in,
                              void* d_out, int out_size) {
    const float* x  = (const float*)d_in[0];
    const float* kc = (const float*)d_in[1];
    const float* vc = (const float*)d_in[2];
    const float* Wq = (const float*)d_in[3];
    const float* Wk = (const float*)d_in[4];
    const float* Wv = (const float*)d_in[5];
    const float* Wo = (const float*)d_in[6];
    const int* seqp = (const int*)d_in[7];
    float* out = (float*)d_out;

    const int attn_smem = ATTN_SMEM_FLOATS * sizeof(float);   // ~71 KB
    cudaFuncSetAttribute(attn_kernel,
                         cudaFuncAttributeMaxDynamicSharedMemorySize, attn_smem);

    rope_table_kernel<<<64, 1024>>>();
    split_kernel<<<512, 256>>>(x);
    mma_gemm_kernel<<<dim3(32, QKV_KSPLIT, 3), 256>>>(Wq, Wk, Wv, QKV_KSPLIT);
    attn_kernel<<<dim3(NB * NH, NSPLIT), 256, attn_smem>>>(kc, vc, seqp);
    combine_kernel<<<NB * NH, 128>>>();
    mma_gemm_kernel<<<dim3(32, 16, 1), 256>>>(Wo, Wo, Wo, 16);
    reduce_kernel<<<128, 256>>>(out, 16);
}